// round 11
// baseline (speedup 1.0000x reference)
#include <cuda_runtime.h>
#include <cuda_bf16.h>
#include <cuda_fp8.h>
#include <cstdint>

// Problem dims (fixed by the dataset)
#define T_DIM 8192
#define H_DIM 2048
#define I_DIM 8192

// ============================ device scratch ================================
__device__ __align__(16) unsigned char g_xq[(size_t)T_DIM * H_DIM];
__device__ __align__(16) unsigned char g_gq[(size_t)I_DIM * H_DIM];
__device__ __align__(16) unsigned char g_uq[(size_t)I_DIM * H_DIM];
__device__ __align__(16) unsigned char g_dq[(size_t)H_DIM * I_DIM];
__device__ __align__(16) __nv_bfloat16 g_inter[(size_t)T_DIM * I_DIM];
__device__ __align__(16) unsigned char g_iq[(size_t)T_DIM * I_DIM];
__device__ float g_amax[8];      // 0:x 1:gate_w 2:up_w 3:down_w 4:inter
__device__ float g_scale_q[8];   // 448/amax
__device__ float g_scale_dq[8];  // 1/(448/amax)

// ============================ helpers =======================================
__device__ __forceinline__ uint32_t smem_u32(const void* p) {
    return (uint32_t)__cvta_generic_to_shared(p);
}

__device__ __forceinline__ void cp_async16(uint32_t saddr, const void* gptr) {
    asm volatile("cp.async.cg.shared.global [%0], [%1], 16;" :: "r"(saddr), "l"(gptr));
}
__device__ __forceinline__ void cp_async_commit() {
    asm volatile("cp.async.commit_group;" ::: "memory");
}
template <int N>
__device__ __forceinline__ void cp_async_wait() {
    asm volatile("cp.async.wait_group %0;" :: "n"(N) : "memory");
}

__device__ __forceinline__ void ldsm_x4(uint32_t* r, uint32_t addr) {
    asm volatile("ldmatrix.sync.aligned.m8n8.x4.shared.b16 {%0,%1,%2,%3}, [%4];"
                 : "=r"(r[0]), "=r"(r[1]), "=r"(r[2]), "=r"(r[3]) : "r"(addr));
}

// fp8 e4m3 x e4m3 -> f32, m16n8k32 (runs on sm_103; validated round 2/10 logs)
__device__ __forceinline__ void mma_fp8(float* c, const uint32_t* a, const uint32_t* b) {
    asm volatile(
        "mma.sync.aligned.m16n8k32.row.col.f32.e4m3.e4m3.f32 "
        "{%0,%1,%2,%3}, {%4,%5,%6,%7}, {%8,%9}, {%0,%1,%2,%3};"
        : "+f"(c[0]), "+f"(c[1]), "+f"(c[2]), "+f"(c[3])
        : "r"(a[0]), "r"(a[1]), "r"(a[2]), "r"(a[3]), "r"(b[0]), "r"(b[1]));
}

__device__ __forceinline__ float bf16r(float x) {
    return __bfloat162float(__float2bfloat16(x));
}

// XLA's EmitFastTanh (Eigen-style rational polynomial) — the exact f32 tanh
// the reference's bf16 tanh upcasts into. Non-FMA Horner, clamp, small-x path.
__device__ __forceinline__ float xla_tanh_f32(float x) {
    const float kMax = 7.90531110763549805f;
    float xc = fminf(fmaxf(x, -kMax), kMax);
    float x2 = __fmul_rn(xc, xc);
    float np = -2.76076847742355e-16f;
    np = __fadd_rn(__fmul_rn(np, x2), 2.00018790482477e-13f);
    np = __fadd_rn(__fmul_rn(np, x2), -8.60467152213735e-11f);
    np = __fadd_rn(__fmul_rn(np, x2), 5.12229709037114e-08f);
    np = __fadd_rn(__fmul_rn(np, x2), 1.48572235717979e-05f);
    np = __fadd_rn(__fmul_rn(np, x2), 6.37261928875436e-04f);
    np = __fadd_rn(__fmul_rn(np, x2), 4.89352455891786e-03f);
    float numerator = __fmul_rn(xc, np);
    float dp = 1.19825839466702e-06f;
    dp = __fadd_rn(__fmul_rn(dp, x2), 1.18534705686654e-04f);
    dp = __fadd_rn(__fmul_rn(dp, x2), 2.26843463243900e-03f);
    dp = __fadd_rn(__fmul_rn(dp, x2), 4.89352518554385e-03f);
    float res = __fdiv_rn(numerator, dp);
    return (fabsf(x) < 0.0004f) ? x : res;
}

// Eager-mode jax.nn.gelu(approximate=True) on bf16: each HLO op rounds bf16.
// integer_pow(x,3) expands to TWO bf16-rounded multiplies.
__device__ __forceinline__ float gelu_bf16_chain(float x /* bf16-valued */) {
    float x2 = bf16r(x * x);
    float x3 = bf16r(x2 * x);
    float t1 = bf16r(0.044677734375f * x3);   // bf16(0.044715)
    float t2 = bf16r(x + t1);
    float t3 = bf16r(0.796875f * t2);         // bf16(sqrt(2/pi))
    float th = bf16r(xla_tanh_f32(t3));
    float t4 = bf16r(1.0f + th);
    float t5 = 0.5f * t4;                     // exact halving
    return bf16r(x * t5);
}

// ============================ small kernels =================================
__global__ void init_amax_kernel() {
    if (threadIdx.x < 8) g_amax[threadIdx.x] = 0.0f;
}

__global__ void amax_kernel(const float* __restrict__ src, int n4, int idx) {
    float m = 0.0f;
    const float4* s = (const float4*)src;
    for (int i = blockIdx.x * blockDim.x + threadIdx.x; i < n4;
         i += gridDim.x * blockDim.x) {
        float4 v = s[i];
        m = fmaxf(m, fmaxf(fmaxf(fabsf(v.x), fabsf(v.y)),
                           fmaxf(fabsf(v.z), fabsf(v.w))));
    }
    #pragma unroll
    for (int o = 16; o; o >>= 1) m = fmaxf(m, __shfl_xor_sync(0xffffffffu, m, o));
    if ((threadIdx.x & 31) == 0)
        atomicMax((unsigned int*)&g_amax[idx], __float_as_uint(m));
}

__global__ void compute_scales_kernel() {
    int i = threadIdx.x;
    if (i < 4) {
        float a = fmaxf(g_amax[i], 1e-12f);
        float s = 448.0f / a;
        g_scale_q[i] = s;
        g_scale_dq[i] = 1.0f / s;
    }
}

__global__ void quant_kernel(const float* __restrict__ src,
                             unsigned char* __restrict__ dst, int n4, int sidx) {
    float s = g_scale_q[sidx];
    const float4* s4 = (const float4*)src;
    uint32_t* d4 = (uint32_t*)dst;
    for (int i = blockIdx.x * blockDim.x + threadIdx.x; i < n4;
         i += gridDim.x * blockDim.x) {
        float4 v = s4[i];
        uint32_t b0 = __nv_cvt_float_to_fp8(v.x * s, __NV_SATFINITE, __NV_E4M3);
        uint32_t b1 = __nv_cvt_float_to_fp8(v.y * s, __NV_SATFINITE, __NV_E4M3);
        uint32_t b2 = __nv_cvt_float_to_fp8(v.z * s, __NV_SATFINITE, __NV_E4M3);
        uint32_t b3 = __nv_cvt_float_to_fp8(v.w * s, __NV_SATFINITE, __NV_E4M3);
        d4[i] = b0 | (b1 << 8) | (b2 << 16) | (b3 << 24);
    }
}

// inter (bf16) -> fp8 bytes; scale chain bf16-rounded (inter is bf16 tensor)
__global__ void quant_inter_kernel(int n8) {
    float amax4 = fmaxf(g_amax[4], 1e-12f);
    float s = bf16r(448.0f / amax4);
    const uint4* src = (const uint4*)g_inter;   // 8 bf16 per uint4
    uint2* dst = (uint2*)g_iq;
    for (int i = blockIdx.x * blockDim.x + threadIdx.x; i < n8;
         i += gridDim.x * blockDim.x) {
        uint4 v = src[i];
        uint32_t words[4] = {v.x, v.y, v.z, v.w};
        uint32_t out[2] = {0u, 0u};
        #pragma unroll
        for (int w = 0; w < 4; w++) {
            float f0 = __bfloat162float(__ushort_as_bfloat16((unsigned short)(words[w] & 0xffffu)));
            float f1 = __bfloat162float(__ushort_as_bfloat16((unsigned short)(words[w] >> 16)));
            uint32_t q0 = __nv_cvt_float_to_fp8(f0 * s, __NV_SATFINITE, __NV_E4M3);
            uint32_t q1 = __nv_cvt_float_to_fp8(f1 * s, __NV_SATFINITE, __NV_E4M3);
            out[w >> 1] |= (q0 | (q1 << 8)) << ((w & 1) * 16);
        }
        dst[i] = make_uint2(out[0], out[1]);
    }
}

// ============================ GEMM kernel ===================================
// CTA tile 128(M) x 128(N), K-chunk 128 bytes, 512 threads = 16 warps (4x4),
// warp tile 32x32. fp8 bytes in smem -> NATIVE m16n8k32 e4m3 mma (f32 acc).
//
// FUSED=true : A=xq, B0=gate_w_q, B1=up_w_q; epilogue bf16 GELU(gate)*up
//              -> g_inter (bf16) + inter amax.
// FUSED=false: single GEMM; epilogue scales, rounds to bf16, writes f32
//              (harness output dtype is float32 = widened bf16 values).

static constexpr int KCH    = 128;              // K bytes per chunk
static constexpr int STRIDE = 144;              // padded smem row stride
static constexpr int TILE   = 128 * STRIDE;     // 18432 B per tile

template <bool FUSED>
__global__ void __launch_bounds__(512, 1)
gemm_fp8_kernel(const unsigned char* __restrict__ A,
                const unsigned char* __restrict__ B0,
                const unsigned char* __restrict__ B1,
                void* __restrict__ out_v,
                int K, int ldo) {
    extern __shared__ __align__(16) char smem[];
    const uint32_t sb = smem_u32(smem);
    const int tid = threadIdx.x;
    const int wid = tid >> 5;
    const int lid = tid & 31;
    const int warp_m = (wid & 3) * 32;
    const int warp_n = (wid >> 2) * 32;
    const int m0 = blockIdx.x * 128;
    const int n0 = blockIdx.y * 128;

    const int NT = FUSED ? 3 : 2;       // tensors per buffer
    const int BUFSZ = NT * TILE;

    auto load_tile = [&](uint32_t sbase, const unsigned char* src, int row0,
                         int k0) {
        const char* base = (const char*)src + (size_t)row0 * K + k0;
        #pragma unroll
        for (int i = 0; i < 2; i++) {
            int c = tid + i * 512;
            int r = c >> 3;
            int s = (c & 7) << 4;
            cp_async16(sbase + r * STRIDE + s, base + (size_t)r * K + s);
        }
    };
    auto load_chunk = [&](int buf, int kc) {
        const uint32_t s0 = sb + buf * BUFSZ;
        const int k0 = kc * KCH;
        load_tile(s0, A, m0, k0);
        load_tile(s0 + TILE, B0, n0, k0);
        if (FUSED) load_tile(s0 + 2 * TILE, B1, n0, k0);
        cp_async_commit();
    };

    // ---- per-lane ldmatrix address components ----
    const int lr = lid & 7;
    const int lg = lid >> 3;
    // A x4: r0=(rows 0-7,k0-15) r1=(rows 8-15,k0-15) r2=(0-7,k16-31) r3=(8-15,k16-31)
    //  -> exactly the m16n8k32 e4m3 A fragment (a0..a3)
    const uint32_t a_lane = (uint32_t)((warp_m + lr + (lg & 1) * 8) * STRIDE +
                                       (lg >> 1) * 16);
    // B x4 over an n-pair: r0=(n0-7,k0-15) r1=(n0-7,k16-31) r2=(n8-15,k0-15) r3=(n8-15,k16-31)
    //  -> (b0,b1) for n-block = regs [0],[1]; +8 n-block = regs [2],[3]
    const uint32_t b_lane = (uint32_t)((warp_n + lr + (lg >> 1) * 8) * STRIDE +
                                       (lg & 1) * 16);

    float accg[2][4][4];
    float accu[FUSED ? 2 : 1][4][4];
    #pragma unroll
    for (int mt = 0; mt < 2; mt++)
        #pragma unroll
        for (int nt = 0; nt < 4; nt++)
            #pragma unroll
            for (int e = 0; e < 4; e++) {
                accg[mt][nt][e] = 0.0f;
                if (FUSED) accu[mt][nt][e] = 0.0f;
            }

    const int NCH = K / KCH;
    load_chunk(0, 0);

    for (int kc = 0; kc < NCH; ++kc) {
        const int buf = kc & 1;
        if (kc + 1 < NCH) {
            load_chunk(buf ^ 1, kc + 1);
            cp_async_wait<1>();
        } else {
            cp_async_wait<0>();
        }
        __syncthreads();

        const uint32_t sA  = sb + buf * BUFSZ;
        const uint32_t sBg = sA + TILE;
        const uint32_t sBu = sBg + TILE;

        #pragma unroll
        for (int ks = 0; ks < 4; ks++) {
            uint32_t af[2][4], bg[2][4];
            #pragma unroll
            for (int mt = 0; mt < 2; mt++)
                ldsm_x4(af[mt], sA + a_lane + mt * 16 * STRIDE + ks * 32);
            #pragma unroll
            for (int p = 0; p < 2; p++)
                ldsm_x4(bg[p], sBg + b_lane + p * 16 * STRIDE + ks * 32);
            #pragma unroll
            for (int mt = 0; mt < 2; mt++)
                #pragma unroll
                for (int nt = 0; nt < 4; nt++)
                    mma_fp8(accg[mt][nt], af[mt], bg[nt >> 1] + (nt & 1) * 2);
            if (FUSED) {
                uint32_t bu[2][4];
                #pragma unroll
                for (int p = 0; p < 2; p++)
                    ldsm_x4(bu[p], sBu + b_lane + p * 16 * STRIDE + ks * 32);
                #pragma unroll
                for (int mt = 0; mt < 2; mt++)
                    #pragma unroll
                    for (int nt = 0; nt < 4; nt++)
                        mma_fp8(accu[mt][nt], af[mt], bu[nt >> 1] + (nt & 1) * 2);
            }
        }
        __syncthreads();
    }

    // ---------------- epilogue ----------------
    // c-frag: c0=(row,col), c1=(row,col+1), c2=(row+8,col), c3=(row+8,col+1)
    const int rbase = m0 + warp_m + (lid >> 2);
    const int cbase = n0 + warp_n + (lid & 3) * 2;

    if (FUSED) {
        __nv_bfloat16* out = (__nv_bfloat16*)out_v;
        const float sA = g_scale_dq[0];
        const float fG = sA * g_scale_dq[1];
        const float fU = sA * g_scale_dq[2];
        float lamax = 0.0f;
        #pragma unroll
        for (int mt = 0; mt < 2; mt++) {
            #pragma unroll
            for (int nt = 0; nt < 4; nt++) {
                #pragma unroll
                for (int half = 0; half < 2; half++) {
                    const int row = rbase + mt * 16 + half * 8;
                    const int col = cbase + nt * 8;
                    uint32_t w = 0;
                    #pragma unroll
                    for (int e = 0; e < 2; e++) {
                        float gf = bf16r(accg[mt][nt][half * 2 + e] * fG);
                        float uf = bf16r(accu[mt][nt][half * 2 + e] * fU);
                        float pb = bf16r(gelu_bf16_chain(gf) * uf);
                        lamax = fmaxf(lamax, fabsf(pb));
                        w |= ((uint32_t)__bfloat16_as_ushort(__float2bfloat16(pb)))
                             << (e * 16);
                    }
                    *(uint32_t*)(out + (size_t)row * ldo + col) = w;
                }
            }
        }
        #pragma unroll
        for (int o = 16; o; o >>= 1)
            lamax = fmaxf(lamax, __shfl_xor_sync(0xffffffffu, lamax, o));
        if (lid == 0)
            atomicMax((unsigned int*)&g_amax[4], __float_as_uint(lamax));
    } else {
        // FINAL OUTPUT IS float32 (= bf16 values widened to f32)
        float* out = (float*)out_v;
        const float amax4 = fmaxf(g_amax[4], 1e-12f);
        const float s4 = bf16r(448.0f / amax4);       // bf16 scale
        const float f = bf16r(1.0f / s4) * g_scale_dq[3];
        #pragma unroll
        for (int mt = 0; mt < 2; mt++) {
            #pragma unroll
            for (int nt = 0; nt < 4; nt++) {
                #pragma unroll
                for (int half = 0; half < 2; half++) {
                    const int row = rbase + mt * 16 + half * 8;
                    const int col = cbase + nt * 8;
                    float2 w;
                    w.x = bf16r(accg[mt][nt][half * 2] * f);
                    w.y = bf16r(accg[mt][nt][half * 2 + 1] * f);
                    *(float2*)(out + (size_t)row * ldo + col) = w;
                }
            }
        }
    }
}

// ============================ launcher ======================================
extern "C" void kernel_launch(void* const* d_in, const int* in_sizes, int n_in,
                              void* d_out, int out_size) {
    const float* x  = (const float*)d_in[0];
    const float* gw = (const float*)d_in[1];
    const float* uw = (const float*)d_in[2];
    const float* dw = (const float*)d_in[3];

    void *p_xq, *p_gq, *p_uq, *p_dq, *p_inter, *p_iq;
    cudaGetSymbolAddress(&p_xq, g_xq);
    cudaGetSymbolAddress(&p_gq, g_gq);
    cudaGetSymbolAddress(&p_uq, g_uq);
    cudaGetSymbolAddress(&p_dq, g_dq);
    cudaGetSymbolAddress(&p_inter, g_inter);
    cudaGetSymbolAddress(&p_iq, g_iq);

    const int SMEM_FUSED = 2 * 3 * TILE;  // 110592
    const int SMEM_PLAIN = 2 * 2 * TILE;  // 73728
    cudaFuncSetAttribute(gemm_fp8_kernel<true>,
                         cudaFuncAttributeMaxDynamicSharedMemorySize, SMEM_FUSED);
    cudaFuncSetAttribute(gemm_fp8_kernel<false>,
                         cudaFuncAttributeMaxDynamicSharedMemorySize, SMEM_PLAIN);

    const int n4 = (T_DIM * H_DIM) / 4;  // each input tensor: 16.7M elems

    init_amax_kernel<<<1, 32>>>();
    amax_kernel<<<1024, 256>>>(x, n4, 0);
    amax_kernel<<<1024, 256>>>(gw, n4, 1);
    amax_kernel<<<1024, 256>>>(uw, n4, 2);
    amax_kernel<<<1024, 256>>>(dw, n4, 3);
    compute_scales_kernel<<<1, 32>>>();
    quant_kernel<<<2048, 256>>>(x, (unsigned char*)p_xq, n4, 0);
    quant_kernel<<<2048, 256>>>(gw, (unsigned char*)p_gq, n4, 1);
    quant_kernel<<<2048, 256>>>(uw, (unsigned char*)p_uq, n4, 2);
    quant_kernel<<<2048, 256>>>(dw, (unsigned char*)p_dq, n4, 3);

    // GEMM1 fused: inter[T, I] = gelu(xq@gq^T * sxg) * (xq@uq^T * sxu) + amax
    gemm_fp8_kernel<true><<<dim3(T_DIM / 128, I_DIM / 128), 512, SMEM_FUSED>>>(
        (const unsigned char*)p_xq, (const unsigned char*)p_gq,
        (const unsigned char*)p_uq, p_inter, H_DIM, I_DIM);

    quant_inter_kernel<<<4096, 256>>>((int)(((size_t)T_DIM * I_DIM) / 8));

    // GEMM2: out_f32[T, H] = widen_bf16((iq @ dq^T) * (i_s*d_s))
    gemm_fp8_kernel<false><<<dim3(T_DIM / 128, H_DIM / 128), 512, SMEM_PLAIN>>>(
        (const unsigned char*)p_iq, (const unsigned char*)p_dq,
        nullptr, d_out, I_DIM, H_DIM);
}

// round 12
// speedup vs baseline: 1.6031x; 1.6031x over previous
#include <cuda_runtime.h>
#include <cuda_bf16.h>
#include <cuda_fp16.h>
#include <cuda_fp8.h>
#include <cstdint>

// Problem dims (fixed by the dataset)
#define T_DIM 8192
#define H_DIM 2048
#define I_DIM 8192

// ============================ device scratch ================================
// Quantized tensors stored as f16 holding EXACT e4m3 values (lossless).
__device__ __align__(16) __half g_xq[(size_t)T_DIM * H_DIM];
__device__ __align__(16) __half g_gq[(size_t)I_DIM * H_DIM];
__device__ __align__(16) __half g_uq[(size_t)I_DIM * H_DIM];
__device__ __align__(16) __half g_dq[(size_t)H_DIM * I_DIM];
__device__ __align__(16) __nv_bfloat16 g_inter[(size_t)T_DIM * I_DIM];
__device__ __align__(16) __half g_iq[(size_t)T_DIM * I_DIM];
__device__ float g_amax[8];      // 0:x 1:gate_w 2:up_w 3:down_w 4:inter
__device__ float g_scale_q[8];   // 448/amax
__device__ float g_scale_dq[8];  // 1/(448/amax)

// ============================ helpers =======================================
__device__ __forceinline__ uint32_t smem_u32(const void* p) {
    return (uint32_t)__cvta_generic_to_shared(p);
}

__device__ __forceinline__ void cp_async16(uint32_t saddr, const void* gptr) {
    asm volatile("cp.async.cg.shared.global [%0], [%1], 16;" :: "r"(saddr), "l"(gptr));
}
__device__ __forceinline__ void cp_async_commit() {
    asm volatile("cp.async.commit_group;" ::: "memory");
}
template <int N>
__device__ __forceinline__ void cp_async_wait() {
    asm volatile("cp.async.wait_group %0;" :: "n"(N) : "memory");
}

__device__ __forceinline__ void ldsm_x4(uint32_t* r, uint32_t addr) {
    asm volatile("ldmatrix.sync.aligned.m8n8.x4.shared.b16 {%0,%1,%2,%3}, [%4];"
                 : "=r"(r[0]), "=r"(r[1]), "=r"(r[2]), "=r"(r[3]) : "r"(addr));
}

// f16 x f16 -> f32 MMA, m16n8k16 (legacy HMMA — the fast path on sm_103)
__device__ __forceinline__ void mma_f16(float* c, const uint32_t* a, const uint32_t* b) {
    asm volatile(
        "mma.sync.aligned.m16n8k16.row.col.f32.f16.f16.f32 "
        "{%0,%1,%2,%3}, {%4,%5,%6,%7}, {%8,%9}, {%0,%1,%2,%3};"
        : "+f"(c[0]), "+f"(c[1]), "+f"(c[2]), "+f"(c[3])
        : "r"(a[0]), "r"(a[1]), "r"(a[2]), "r"(a[3]), "r"(b[0]), "r"(b[1]));
}

__device__ __forceinline__ float bf16r(float x) {
    return __bfloat162float(__float2bfloat16(x));
}

// f32 -> e4m3 (round-nearest, satfinite) -> exact f16 value of that e4m3
__device__ __forceinline__ unsigned short quant_h(float v, float s) {
    __nv_fp8_storage_t q = __nv_cvt_float_to_fp8(v * s, __NV_SATFINITE, __NV_E4M3);
    __half_raw hr = __nv_cvt_fp8_to_halfraw(q, __NV_E4M3);
    return hr.x;
}

// XLA's EmitFastTanh (Eigen-style rational polynomial) — the exact f32 tanh
// the reference's bf16 tanh upcasts into. Non-FMA Horner, clamp, small-x path.
__device__ __forceinline__ float xla_tanh_f32(float x) {
    const float kMax = 7.90531110763549805f;
    float xc = fminf(fmaxf(x, -kMax), kMax);
    float x2 = __fmul_rn(xc, xc);
    float np = -2.76076847742355e-16f;
    np = __fadd_rn(__fmul_rn(np, x2), 2.00018790482477e-13f);
    np = __fadd_rn(__fmul_rn(np, x2), -8.60467152213735e-11f);
    np = __fadd_rn(__fmul_rn(np, x2), 5.12229709037114e-08f);
    np = __fadd_rn(__fmul_rn(np, x2), 1.48572235717979e-05f);
    np = __fadd_rn(__fmul_rn(np, x2), 6.37261928875436e-04f);
    np = __fadd_rn(__fmul_rn(np, x2), 4.89352455891786e-03f);
    float numerator = __fmul_rn(xc, np);
    float dp = 1.19825839466702e-06f;
    dp = __fadd_rn(__fmul_rn(dp, x2), 1.18534705686654e-04f);
    dp = __fadd_rn(__fmul_rn(dp, x2), 2.26843463243900e-03f);
    dp = __fadd_rn(__fmul_rn(dp, x2), 4.89352518554385e-03f);
    float res = __fdiv_rn(numerator, dp);
    return (fabsf(x) < 0.0004f) ? x : res;
}

// Eager-mode jax.nn.gelu(approximate=True) on bf16: each HLO op rounds bf16.
// integer_pow(x,3) expands to TWO bf16-rounded multiplies.
__device__ __forceinline__ float gelu_bf16_chain(float x /* bf16-valued */) {
    float x2 = bf16r(x * x);
    float x3 = bf16r(x2 * x);
    float t1 = bf16r(0.044677734375f * x3);   // bf16(0.044715)
    float t2 = bf16r(x + t1);
    float t3 = bf16r(0.796875f * t2);         // bf16(sqrt(2/pi))
    float th = bf16r(xla_tanh_f32(t3));
    float t4 = bf16r(1.0f + th);
    float t5 = 0.5f * t4;                     // exact halving
    return bf16r(x * t5);
}

// ============================ small kernels =================================
__global__ void init_amax_kernel() {
    if (threadIdx.x < 8) g_amax[threadIdx.x] = 0.0f;
}

__global__ void amax_kernel(const float* __restrict__ src, int n4, int idx) {
    float m0 = 0.0f, m1 = 0.0f;
    const float4* s = (const float4*)src;
    int stride = gridDim.x * blockDim.x;
    int i = blockIdx.x * blockDim.x + threadIdx.x;
    for (; i + stride < n4; i += 2 * stride) {
        float4 v0 = s[i];
        float4 v1 = s[i + stride];
        m0 = fmaxf(m0, fmaxf(fmaxf(fabsf(v0.x), fabsf(v0.y)),
                             fmaxf(fabsf(v0.z), fabsf(v0.w))));
        m1 = fmaxf(m1, fmaxf(fmaxf(fabsf(v1.x), fabsf(v1.y)),
                             fmaxf(fabsf(v1.z), fabsf(v1.w))));
    }
    if (i < n4) {
        float4 v = s[i];
        m0 = fmaxf(m0, fmaxf(fmaxf(fabsf(v.x), fabsf(v.y)),
                             fmaxf(fabsf(v.z), fabsf(v.w))));
    }
    float m = fmaxf(m0, m1);
    #pragma unroll
    for (int o = 16; o; o >>= 1) m = fmaxf(m, __shfl_xor_sync(0xffffffffu, m, o));
    if ((threadIdx.x & 31) == 0)
        atomicMax((unsigned int*)&g_amax[idx], __float_as_uint(m));
}

__global__ void compute_scales_kernel() {
    int i = threadIdx.x;
    if (i < 4) {
        float a = fmaxf(g_amax[i], 1e-12f);
        float s = 448.0f / a;
        g_scale_q[i] = s;
        g_scale_dq[i] = 1.0f / s;
    }
}

// f32 -> e4m3-valued f16
__global__ void quant_kernel(const float* __restrict__ src,
                             __half* __restrict__ dst, int n4, int sidx) {
    float s = g_scale_q[sidx];
    const float4* s4 = (const float4*)src;
    uint2* d2 = (uint2*)dst;
    for (int i = blockIdx.x * blockDim.x + threadIdx.x; i < n4;
         i += gridDim.x * blockDim.x) {
        float4 v = s4[i];
        uint2 o;
        o.x = (uint32_t)quant_h(v.x, s) | ((uint32_t)quant_h(v.y, s) << 16);
        o.y = (uint32_t)quant_h(v.z, s) | ((uint32_t)quant_h(v.w, s) << 16);
        d2[i] = o;
    }
}

// inter (bf16) -> e4m3-valued f16; scale chain bf16-rounded
__global__ void quant_inter_kernel(int n8) {
    float amax4 = fmaxf(g_amax[4], 1e-12f);
    float s = bf16r(448.0f / amax4);
    const uint4* src = (const uint4*)g_inter;   // 8 bf16 per uint4
    uint4* dst = (uint4*)g_iq;                  // 8 f16 per uint4
    for (int i = blockIdx.x * blockDim.x + threadIdx.x; i < n8;
         i += gridDim.x * blockDim.x) {
        uint4 v = src[i];
        uint32_t words[4] = {v.x, v.y, v.z, v.w};
        uint32_t ow[4];
        #pragma unroll
        for (int w = 0; w < 4; w++) {
            float f0 = __bfloat162float(__ushort_as_bfloat16((unsigned short)(words[w] & 0xffffu)));
            float f1 = __bfloat162float(__ushort_as_bfloat16((unsigned short)(words[w] >> 16)));
            ow[w] = (uint32_t)quant_h(f0, s) | ((uint32_t)quant_h(f1, s) << 16);
        }
        dst[i] = make_uint4(ow[0], ow[1], ow[2], ow[3]);
    }
}

// ============================ GEMM kernel ===================================
// CTA tile 128(M) x 128(N), K-chunk 128 elements (256 B rows, f16), 512
// threads = 16 warps (4x4), warp tile 32x32. f16 data (exact e4m3 values)
// -> ldsm feeds m16n8k16 f32-acc HMMA directly. NO cvt in the mainloop.
//
// FUSED=true : A=xq, B0=gate_w_q, B1=up_w_q; epilogue bf16 GELU(gate)*up
//              -> g_inter (bf16) + inter amax.
// FUSED=false: single GEMM; epilogue scales, rounds to bf16, writes f32
//              (harness output dtype is float32 = widened bf16 values).

static constexpr int KCH    = 128;              // K elements per chunk
static constexpr int ROWB   = KCH * 2;          // 256 bytes per row
static constexpr int STRIDE = ROWB + 16;        // 272-byte padded stride
static constexpr int TILE   = 128 * STRIDE;     // 34816 B per tile

template <bool FUSED>
__global__ void __launch_bounds__(512, 1)
gemm_f16_kernel(const __half* __restrict__ A,
                const __half* __restrict__ B0,
                const __half* __restrict__ B1,
                void* __restrict__ out_v,
                int K, int ldo) {
    extern __shared__ __align__(16) char smem[];
    const uint32_t sb = smem_u32(smem);
    const int tid = threadIdx.x;
    const int wid = tid >> 5;
    const int lid = tid & 31;
    const int warp_m = (wid & 3) * 32;
    const int warp_n = (wid >> 2) * 32;
    const int m0 = blockIdx.x * 128;
    const int n0 = blockIdx.y * 128;

    const int NT = FUSED ? 3 : 2;       // tensors per buffer
    const int BUFSZ = NT * TILE;

    // tile: 128 rows x 256 B = 2048 x 16B chunks, 512 threads -> 4 each
    auto load_tile = [&](uint32_t sbase, const __half* src, int row0, int k0) {
        const char* base = (const char*)(src + (size_t)row0 * K + k0);
        #pragma unroll
        for (int i = 0; i < 4; i++) {
            int c = tid + i * 512;          // 0..2047
            int r = c >> 4;                 // 0..127
            int s = (c & 15) << 4;          // 0..240 bytes
            cp_async16(sbase + r * STRIDE + s, base + (size_t)r * K * 2 + s);
        }
    };
    auto load_chunk = [&](int buf, int kc) {
        const uint32_t s0 = sb + buf * BUFSZ;
        const int k0 = kc * KCH;
        load_tile(s0, A, m0, k0);
        load_tile(s0 + TILE, B0, n0, k0);
        if (FUSED) load_tile(s0 + 2 * TILE, B1, n0, k0);
        cp_async_commit();
    };

    // ---- per-lane ldmatrix address components (validated r3/r10 layout) ----
    const int lr = lid & 7;
    const int lg = lid >> 3;
    // A x4 per k16: r0=(rows0-7,k0-7) r1=(rows8-15,k0-7) r2=(0-7,k8-15) r3=(8-15,k8-15)
    const uint32_t a_lane = (uint32_t)((warp_m + lr + (lg & 1) * 8) * STRIDE +
                                       (lg >> 1) * 16);
    // B x4 per n-pair per k16: r0=(n0-7,k0-7) r1=(n0-7,k8-15) r2=(n8-15,k0-7) r3=(n8-15,k8-15)
    const uint32_t b_lane = (uint32_t)((warp_n + lr + (lg >> 1) * 8) * STRIDE +
                                       (lg & 1) * 16);

    float accg[2][4][4];
    float accu[FUSED ? 2 : 1][4][4];
    #pragma unroll
    for (int mt = 0; mt < 2; mt++)
        #pragma unroll
        for (int nt = 0; nt < 4; nt++)
            #pragma unroll
            for (int e = 0; e < 4; e++) {
                accg[mt][nt][e] = 0.0f;
                if (FUSED) accu[mt][nt][e] = 0.0f;
            }

    const int NCH = K / KCH;
    load_chunk(0, 0);

    for (int kc = 0; kc < NCH; ++kc) {
        const int buf = kc & 1;
        if (kc + 1 < NCH) {
            load_chunk(buf ^ 1, kc + 1);
            cp_async_wait<1>();
        } else {
            cp_async_wait<0>();
        }
        __syncthreads();

        const uint32_t sA  = sb + buf * BUFSZ;
        const uint32_t sBg = sA + TILE;
        const uint32_t sBu = sBg + TILE;

        #pragma unroll
        for (int ks = 0; ks < 8; ks++) {      // 8 k16 steps per 128-elem chunk
            const uint32_t ko = ks * 32;      // 16 f16 = 32 bytes
            uint32_t af[2][4], bg[2][4];
            #pragma unroll
            for (int mt = 0; mt < 2; mt++)
                ldsm_x4(af[mt], sA + a_lane + mt * 16 * STRIDE + ko);
            #pragma unroll
            for (int p = 0; p < 2; p++)
                ldsm_x4(bg[p], sBg + b_lane + p * 16 * STRIDE + ko);
            #pragma unroll
            for (int mt = 0; mt < 2; mt++)
                #pragma unroll
                for (int nt = 0; nt < 4; nt++)
                    mma_f16(accg[mt][nt], af[mt], bg[nt >> 1] + (nt & 1) * 2);
            if (FUSED) {
                uint32_t bu[2][4];
                #pragma unroll
                for (int p = 0; p < 2; p++)
                    ldsm_x4(bu[p], sBu + b_lane + p * 16 * STRIDE + ko);
                #pragma unroll
                for (int mt = 0; mt < 2; mt++)
                    #pragma unroll
                    for (int nt = 0; nt < 4; nt++)
                        mma_f16(accu[mt][nt], af[mt], bu[nt >> 1] + (nt & 1) * 2);
            }
        }
        __syncthreads();
    }

    // ---------------- epilogue ----------------
    // c-frag: c0=(row,col), c1=(row,col+1), c2=(row+8,col), c3=(row+8,col+1)
    const int rbase = m0 + warp_m + (lid >> 2);
    const int cbase = n0 + warp_n + (lid & 3) * 2;

    if (FUSED) {
        __nv_bfloat16* out = (__nv_bfloat16*)out_v;
        const float sA = g_scale_dq[0];
        const float fG = sA * g_scale_dq[1];
        const float fU = sA * g_scale_dq[2];
        float lamax = 0.0f;
        #pragma unroll
        for (int mt = 0; mt < 2; mt++) {
            #pragma unroll
            for (int nt = 0; nt < 4; nt++) {
                #pragma unroll
                for (int half = 0; half < 2; half++) {
                    const int row = rbase + mt * 16 + half * 8;
                    const int col = cbase + nt * 8;
                    uint32_t w = 0;
                    #pragma unroll
                    for (int e = 0; e < 2; e++) {
                        float gf = bf16r(accg[mt][nt][half * 2 + e] * fG);
                        float uf = bf16r(accu[mt][nt][half * 2 + e] * fU);
                        float pb = bf16r(gelu_bf16_chain(gf) * uf);
                        lamax = fmaxf(lamax, fabsf(pb));
                        w |= ((uint32_t)__bfloat16_as_ushort(__float2bfloat16(pb)))
                             << (e * 16);
                    }
                    *(uint32_t*)(out + (size_t)row * ldo + col) = w;
                }
            }
        }
        #pragma unroll
        for (int o = 16; o; o >>= 1)
            lamax = fmaxf(lamax, __shfl_xor_sync(0xffffffffu, lamax, o));
        if (lid == 0)
            atomicMax((unsigned int*)&g_amax[4], __float_as_uint(lamax));
    } else {
        // FINAL OUTPUT IS float32 (= bf16 values widened to f32)
        float* out = (float*)out_v;
        const float amax4 = fmaxf(g_amax[4], 1e-12f);
        const float s4 = bf16r(448.0f / amax4);       // bf16 scale
        const float f = bf16r(1.0f / s4) * g_scale_dq[3];
        #pragma unroll
        for (int mt = 0; mt < 2; mt++) {
            #pragma unroll
            for (int nt = 0; nt < 4; nt++) {
                #pragma unroll
                for (int half = 0; half < 2; half++) {
                    const int row = rbase + mt * 16 + half * 8;
                    const int col = cbase + nt * 8;
                    float2 w;
                    w.x = bf16r(accg[mt][nt][half * 2] * f);
                    w.y = bf16r(accg[mt][nt][half * 2 + 1] * f);
                    *(float2*)(out + (size_t)row * ldo + col) = w;
                }
            }
        }
    }
}

// ============================ launcher ======================================
extern "C" void kernel_launch(void* const* d_in, const int* in_sizes, int n_in,
                              void* d_out, int out_size) {
    const float* x  = (const float*)d_in[0];
    const float* gw = (const float*)d_in[1];
    const float* uw = (const float*)d_in[2];
    const float* dw = (const float*)d_in[3];

    void *p_xq, *p_gq, *p_uq, *p_dq, *p_inter, *p_iq;
    cudaGetSymbolAddress(&p_xq, g_xq);
    cudaGetSymbolAddress(&p_gq, g_gq);
    cudaGetSymbolAddress(&p_uq, g_uq);
    cudaGetSymbolAddress(&p_dq, g_dq);
    cudaGetSymbolAddress(&p_inter, g_inter);
    cudaGetSymbolAddress(&p_iq, g_iq);

    const int SMEM_FUSED = 2 * 3 * TILE;  // 208896
    const int SMEM_PLAIN = 2 * 2 * TILE;  // 139264
    cudaFuncSetAttribute(gemm_f16_kernel<true>,
                         cudaFuncAttributeMaxDynamicSharedMemorySize, SMEM_FUSED);
    cudaFuncSetAttribute(gemm_f16_kernel<false>,
                         cudaFuncAttributeMaxDynamicSharedMemorySize, SMEM_PLAIN);

    const int n4 = (T_DIM * H_DIM) / 4;  // each input tensor: 16.7M elems

    init_amax_kernel<<<1, 32>>>();
    amax_kernel<<<2048, 256>>>(x, n4, 0);
    amax_kernel<<<2048, 256>>>(gw, n4, 1);
    amax_kernel<<<2048, 256>>>(uw, n4, 2);
    amax_kernel<<<2048, 256>>>(dw, n4, 3);
    compute_scales_kernel<<<1, 32>>>();
    quant_kernel<<<2048, 256>>>(x, (__half*)p_xq, n4, 0);
    quant_kernel<<<2048, 256>>>(gw, (__half*)p_gq, n4, 1);
    quant_kernel<<<2048, 256>>>(uw, (__half*)p_uq, n4, 2);
    quant_kernel<<<2048, 256>>>(dw, (__half*)p_dq, n4, 3);

    // GEMM1 fused: inter[T, I] = gelu(xq@gq^T * sxg) * (xq@uq^T * sxu) + amax
    gemm_f16_kernel<true><<<dim3(T_DIM / 128, I_DIM / 128), 512, SMEM_FUSED>>>(
        (const __half*)p_xq, (const __half*)p_gq,
        (const __half*)p_uq, p_inter, H_DIM, I_DIM);

    quant_inter_kernel<<<4096, 256>>>((int)(((size_t)T_DIM * I_DIM) / 8));

    // GEMM2: out_f32[T, H] = widen_bf16((iq @ dq^T) * (i_s*d_s))
    gemm_f16_kernel<false><<<dim3(T_DIM / 128, H_DIM / 128), 512, SMEM_PLAIN>>>(
        (const __half*)p_iq, (const __half*)p_dq,
        nullptr, d_out, I_DIM, H_DIM);
}

// round 13
// speedup vs baseline: 1.8580x; 1.1590x over previous
#include <cuda_runtime.h>
#include <cuda_bf16.h>
#include <cuda_fp8.h>
#include <cstdint>

// Problem dims (fixed by the dataset)
#define T_DIM 8192
#define H_DIM 2048
#define I_DIM 8192

// ============================ device scratch ================================
__device__ __align__(16) unsigned char g_xq[(size_t)T_DIM * H_DIM];
__device__ __align__(16) unsigned char g_gq[(size_t)I_DIM * H_DIM];
__device__ __align__(16) unsigned char g_uq[(size_t)I_DIM * H_DIM];
__device__ __align__(16) unsigned char g_dq[(size_t)H_DIM * I_DIM];
__device__ __align__(16) __nv_bfloat16 g_inter[(size_t)T_DIM * I_DIM];
__device__ __align__(16) unsigned char g_iq[(size_t)T_DIM * I_DIM];
__device__ float g_amax[8];      // 0:x 1:gate_w 2:up_w 3:down_w 4:inter
__device__ float g_scale_q[8];   // 448/amax
__device__ float g_scale_dq[8];  // 1/(448/amax)

// ============================ helpers =======================================
__device__ __forceinline__ uint32_t smem_u32(const void* p) {
    return (uint32_t)__cvta_generic_to_shared(p);
}

__device__ __forceinline__ void cp_async16(uint32_t saddr, const void* gptr) {
    asm volatile("cp.async.cg.shared.global [%0], [%1], 16;" :: "r"(saddr), "l"(gptr));
}
__device__ __forceinline__ void cp_async_commit() {
    asm volatile("cp.async.commit_group;" ::: "memory");
}
template <int N>
__device__ __forceinline__ void cp_async_wait() {
    asm volatile("cp.async.wait_group %0;" :: "n"(N) : "memory");
}

// volatile: must not move across barriers (reads smem filled by cp.async)
__device__ __forceinline__ void ldsm_x4(uint32_t* r, uint32_t addr) {
    asm volatile("ldmatrix.sync.aligned.m8n8.x4.shared.b16 {%0,%1,%2,%3}, [%4];"
                 : "=r"(r[0]), "=r"(r[1]), "=r"(r[2]), "=r"(r[3]) : "r"(addr));
}

// 4 packed e4m3 bytes -> two f16x2 regs (lo = bytes 0,1; hi = bytes 2,3).
// NON-volatile: pure register op, scheduler may move it.
__device__ __forceinline__ void cvt8(uint32_t v, uint32_t& lo, uint32_t& hi) {
    asm("{\n\t"
        ".reg .b16 l, h;\n\t"
        "mov.b32 {l, h}, %2;\n\t"
        "cvt.rn.f16x2.e4m3x2 %0, l;\n\t"
        "cvt.rn.f16x2.e4m3x2 %1, h;\n\t"
        "}"
        : "=r"(lo), "=r"(hi) : "r"(v));
}

// f16 x f16 -> f32 MMA, m16n8k16. NON-volatile: pure register op — lets
// ptxas interleave MMAs with the following ldsm/cvt stream (software
// pipelining across the unrolled k loop).
__device__ __forceinline__ void mma_f16(float* c, const uint32_t* a, const uint32_t* b) {
    asm("mma.sync.aligned.m16n8k16.row.col.f32.f16.f16.f32 "
        "{%0,%1,%2,%3}, {%4,%5,%6,%7}, {%8,%9}, {%0,%1,%2,%3};"
        : "+f"(c[0]), "+f"(c[1]), "+f"(c[2]), "+f"(c[3])
        : "r"(a[0]), "r"(a[1]), "r"(a[2]), "r"(a[3]), "r"(b[0]), "r"(b[1]));
}

__device__ __forceinline__ float bf16r(float x) {
    return __bfloat162float(__float2bfloat16(x));
}

// XLA's EmitFastTanh (Eigen-style rational polynomial).
__device__ __forceinline__ float xla_tanh_f32(float x) {
    const float kMax = 7.90531110763549805f;
    float xc = fminf(fmaxf(x, -kMax), kMax);
    float x2 = __fmul_rn(xc, xc);
    float np = -2.76076847742355e-16f;
    np = __fadd_rn(__fmul_rn(np, x2), 2.00018790482477e-13f);
    np = __fadd_rn(__fmul_rn(np, x2), -8.60467152213735e-11f);
    np = __fadd_rn(__fmul_rn(np, x2), 5.12229709037114e-08f);
    np = __fadd_rn(__fmul_rn(np, x2), 1.48572235717979e-05f);
    np = __fadd_rn(__fmul_rn(np, x2), 6.37261928875436e-04f);
    np = __fadd_rn(__fmul_rn(np, x2), 4.89352455891786e-03f);
    float numerator = __fmul_rn(xc, np);
    float dp = 1.19825839466702e-06f;
    dp = __fadd_rn(__fmul_rn(dp, x2), 1.18534705686654e-04f);
    dp = __fadd_rn(__fmul_rn(dp, x2), 2.26843463243900e-03f);
    dp = __fadd_rn(__fmul_rn(dp, x2), 4.89352518554385e-03f);
    float res = __fdiv_rn(numerator, dp);
    return (fabsf(x) < 0.0004f) ? x : res;
}

// Eager-mode jax.nn.gelu(approximate=True) on bf16: each HLO op rounds bf16.
// integer_pow(x,3) expands to TWO bf16-rounded multiplies.
__device__ __forceinline__ float gelu_bf16_chain(float x /* bf16-valued */) {
    float x2 = bf16r(x * x);
    float x3 = bf16r(x2 * x);
    float t1 = bf16r(0.044677734375f * x3);   // bf16(0.044715)
    float t2 = bf16r(x + t1);
    float t3 = bf16r(0.796875f * t2);         // bf16(sqrt(2/pi))
    float th = bf16r(xla_tanh_f32(t3));
    float t4 = bf16r(1.0f + th);
    float t5 = 0.5f * t4;                     // exact halving
    return bf16r(x * t5);
}

// ============================ small kernels =================================
__global__ void init_amax_kernel() {
    if (threadIdx.x < 8) g_amax[threadIdx.x] = 0.0f;
}

__global__ void amax_kernel(const float* __restrict__ src, int n4, int idx) {
    float m = 0.0f;
    const float4* s = (const float4*)src;
    for (int i = blockIdx.x * blockDim.x + threadIdx.x; i < n4;
         i += gridDim.x * blockDim.x) {
        float4 v = s[i];
        m = fmaxf(m, fmaxf(fmaxf(fabsf(v.x), fabsf(v.y)),
                           fmaxf(fabsf(v.z), fabsf(v.w))));
    }
    #pragma unroll
    for (int o = 16; o; o >>= 1) m = fmaxf(m, __shfl_xor_sync(0xffffffffu, m, o));
    if ((threadIdx.x & 31) == 0)
        atomicMax((unsigned int*)&g_amax[idx], __float_as_uint(m));
}

__global__ void compute_scales_kernel() {
    int i = threadIdx.x;
    if (i < 4) {
        float a = fmaxf(g_amax[i], 1e-12f);
        float s = 448.0f / a;
        g_scale_q[i] = s;
        g_scale_dq[i] = 1.0f / s;
    }
}

__global__ void quant_kernel(const float* __restrict__ src,
                             unsigned char* __restrict__ dst, int n4, int sidx) {
    float s = g_scale_q[sidx];
    const float4* s4 = (const float4*)src;
    uint32_t* d4 = (uint32_t*)dst;
    for (int i = blockIdx.x * blockDim.x + threadIdx.x; i < n4;
         i += gridDim.x * blockDim.x) {
        float4 v = s4[i];
        uint32_t b0 = __nv_cvt_float_to_fp8(v.x * s, __NV_SATFINITE, __NV_E4M3);
        uint32_t b1 = __nv_cvt_float_to_fp8(v.y * s, __NV_SATFINITE, __NV_E4M3);
        uint32_t b2 = __nv_cvt_float_to_fp8(v.z * s, __NV_SATFINITE, __NV_E4M3);
        uint32_t b3 = __nv_cvt_float_to_fp8(v.w * s, __NV_SATFINITE, __NV_E4M3);
        d4[i] = b0 | (b1 << 8) | (b2 << 16) | (b3 << 24);
    }
}

// inter (bf16) -> fp8 bytes; scale chain bf16-rounded (inter is bf16 tensor)
__global__ void quant_inter_kernel(int n8) {
    float amax4 = fmaxf(g_amax[4], 1e-12f);
    float s = bf16r(448.0f / amax4);
    const uint4* src = (const uint4*)g_inter;   // 8 bf16 per uint4
    uint2* dst = (uint2*)g_iq;
    for (int i = blockIdx.x * blockDim.x + threadIdx.x; i < n8;
         i += gridDim.x * blockDim.x) {
        uint4 v = src[i];
        uint32_t words[4] = {v.x, v.y, v.z, v.w};
        uint32_t out[2] = {0u, 0u};
        #pragma unroll
        for (int w = 0; w < 4; w++) {
            float f0 = __bfloat162float(__ushort_as_bfloat16((unsigned short)(words[w] & 0xffffu)));
            float f1 = __bfloat162float(__ushort_as_bfloat16((unsigned short)(words[w] >> 16)));
            uint32_t q0 = __nv_cvt_float_to_fp8(f0 * s, __NV_SATFINITE, __NV_E4M3);
            uint32_t q1 = __nv_cvt_float_to_fp8(f1 * s, __NV_SATFINITE, __NV_E4M3);
            out[w >> 1] |= (q0 | (q1 << 8)) << ((w & 1) * 16);
        }
        dst[i] = make_uint2(out[0], out[1]);
    }
}

// ============================ GEMM kernel ===================================
// CTA tile 128(M) x 128(N), K-chunk 128 bytes, 512 threads = 16 warps (4x4),
// warp tile 32x32. fp8 bytes in smem -> exact f16 via cvt -> m16n8k16 HMMA.
// THREE-stage cp.async pipeline (buffers 0/1/2, wait_group 1).
//
// FUSED=true : A=xq, B0=gate_w_q, B1=up_w_q; epilogue bf16 GELU(gate)*up
//              -> g_inter (bf16) + inter amax.
// FUSED=false: single GEMM; epilogue scales, rounds to bf16, writes f32.

static constexpr int KCH    = 128;              // K bytes per chunk
static constexpr int STRIDE = 144;              // padded smem row stride
static constexpr int TILE   = 128 * STRIDE;     // 18432 B per tile
static constexpr int NSTAGE = 3;

template <bool FUSED>
__global__ void __launch_bounds__(512, 1)
gemm_fp8_kernel(const unsigned char* __restrict__ A,
                const unsigned char* __restrict__ B0,
                const unsigned char* __restrict__ B1,
                void* __restrict__ out_v,
                int K, int ldo) {
    extern __shared__ __align__(16) char smem[];
    const uint32_t sb = smem_u32(smem);
    const int tid = threadIdx.x;
    const int wid = tid >> 5;
    const int lid = tid & 31;
    const int warp_m = (wid & 3) * 32;
    const int warp_n = (wid >> 2) * 32;
    const int m0 = blockIdx.x * 128;
    const int n0 = blockIdx.y * 128;

    const int NT = FUSED ? 3 : 2;       // tensors per buffer
    const int BUFSZ = NT * TILE;

    auto load_tile = [&](uint32_t sbase, const unsigned char* src, int row0,
                         int k0) {
        const char* base = (const char*)src + (size_t)row0 * K + k0;
        #pragma unroll
        for (int i = 0; i < 2; i++) {
            int c = tid + i * 512;
            int r = c >> 3;
            int s = (c & 7) << 4;
            cp_async16(sbase + r * STRIDE + s, base + (size_t)r * K + s);
        }
    };
    auto load_chunk = [&](int buf, int kc) {
        const uint32_t s0 = sb + buf * BUFSZ;
        const int k0 = kc * KCH;
        load_tile(s0, A, m0, k0);
        load_tile(s0 + TILE, B0, n0, k0);
        if (FUSED) load_tile(s0 + 2 * TILE, B1, n0, k0);
        cp_async_commit();
    };

    // ---- per-lane ldmatrix address components ----
    const int lr = lid & 7;
    const int lg = lid >> 3;
    const uint32_t a_lane = (uint32_t)((warp_m + lr + (lg & 1) * 8) * STRIDE +
                                       (lg >> 1) * 16);
    const uint32_t b_lane = (uint32_t)((warp_n + lr + (lg >> 1) * 8) * STRIDE +
                                       (lg & 1) * 16);

    float accg[2][4][4];
    float accu[FUSED ? 2 : 1][4][4];
    #pragma unroll
    for (int mt = 0; mt < 2; mt++)
        #pragma unroll
        for (int nt = 0; nt < 4; nt++)
            #pragma unroll
            for (int e = 0; e < 4; e++) {
                accg[mt][nt][e] = 0.0f;
                if (FUSED) accu[mt][nt][e] = 0.0f;
            }

    const int NCH = K / KCH;
    // prologue: prefetch chunks 0 and 1
    load_chunk(0, 0);
    load_chunk(1, 1);

    for (int kc = 0; kc < NCH; ++kc) {
        const int buf = kc % NSTAGE;
        // ensure chunk kc's data has landed (allow 1 pending = chunk kc+1)
        if (kc + 1 < NCH) cp_async_wait<1>();
        else              cp_async_wait<0>();
        __syncthreads();   // also: all warps done computing chunk kc-1

        // prefetch chunk kc+2 into buffer (kc+2)%3 (last used by chunk kc-1)
        if (kc + 2 < NCH) load_chunk((kc + 2) % NSTAGE, kc + 2);

        const uint32_t sA  = sb + buf * BUFSZ;
        const uint32_t sBg = sA + TILE;
        const uint32_t sBu = sBg + TILE;

        #pragma unroll
        for (int ks = 0; ks < 4; ks++) {
            uint32_t af[2][4];
            #pragma unroll
            for (int mt = 0; mt < 2; mt++)
                ldsm_x4(af[mt], sA + a_lane + mt * 16 * STRIDE + ks * 32);
            uint32_t a16[2][2][4];   // [khalf][mt][4 regs]
            #pragma unroll
            for (int mt = 0; mt < 2; mt++) {
                cvt8(af[mt][0], a16[0][mt][0], a16[0][mt][2]);
                cvt8(af[mt][1], a16[0][mt][1], a16[0][mt][3]);
                cvt8(af[mt][2], a16[1][mt][0], a16[1][mt][2]);
                cvt8(af[mt][3], a16[1][mt][1], a16[1][mt][3]);
            }

            #pragma unroll
            for (int p = 0; p < 2; p++) {
                uint32_t bq[4];
                ldsm_x4(bq, sBg + b_lane + p * 16 * STRIDE + ks * 32);
                #pragma unroll
                for (int half = 0; half < 2; half++) {
                    uint32_t B0r[2], B1r[2];
                    cvt8(bq[2 * half],     B0r[0], B0r[1]);   // k 0-15
                    cvt8(bq[2 * half + 1], B1r[0], B1r[1]);   // k 16-31
                    const int nt = p * 2 + half;
                    #pragma unroll
                    for (int mt = 0; mt < 2; mt++) {
                        mma_f16(accg[mt][nt], a16[0][mt], B0r);
                        mma_f16(accg[mt][nt], a16[1][mt], B1r);
                    }
                }
            }
            if (FUSED) {
                #pragma unroll
                for (int p = 0; p < 2; p++) {
                    uint32_t bq[4];
                    ldsm_x4(bq, sBu + b_lane + p * 16 * STRIDE + ks * 32);
                    #pragma unroll
                    for (int half = 0; half < 2; half++) {
                        uint32_t B0r[2], B1r[2];
                        cvt8(bq[2 * half],     B0r[0], B0r[1]);
                        cvt8(bq[2 * half + 1], B1r[0], B1r[1]);
                        const int nt = p * 2 + half;
                        #pragma unroll
                        for (int mt = 0; mt < 2; mt++) {
                            mma_f16(accu[mt][nt], a16[0][mt], B0r);
                            mma_f16(accu[mt][nt], a16[1][mt], B1r);
                        }
                    }
                }
            }
        }
    }

    // ---------------- epilogue ----------------
    const int rbase = m0 + warp_m + (lid >> 2);
    const int cbase = n0 + warp_n + (lid & 3) * 2;

    if (FUSED) {
        __nv_bfloat16* out = (__nv_bfloat16*)out_v;
        const float sA = g_scale_dq[0];
        const float fG = sA * g_scale_dq[1];
        const float fU = sA * g_scale_dq[2];
        float lamax = 0.0f;
        #pragma unroll
        for (int mt = 0; mt < 2; mt++) {
            #pragma unroll
            for (int nt = 0; nt < 4; nt++) {
                #pragma unroll
                for (int half = 0; half < 2; half++) {
                    const int row = rbase + mt * 16 + half * 8;
                    const int col = cbase + nt * 8;
                    uint32_t w = 0;
                    #pragma unroll
                    for (int e = 0; e < 2; e++) {
                        float gf = bf16r(accg[mt][nt][half * 2 + e] * fG);
                        float uf = bf16r(accu[mt][nt][half * 2 + e] * fU);
                        float pb = bf16r(gelu_bf16_chain(gf) * uf);
                        lamax = fmaxf(lamax, fabsf(pb));
                        w |= ((uint32_t)__bfloat16_as_ushort(__float2bfloat16(pb)))
                             << (e * 16);
                    }
                    *(uint32_t*)(out + (size_t)row * ldo + col) = w;
                }
            }
        }
        #pragma unroll
        for (int o = 16; o; o >>= 1)
            lamax = fmaxf(lamax, __shfl_xor_sync(0xffffffffu, lamax, o));
        if (lid == 0)
            atomicMax((unsigned int*)&g_amax[4], __float_as_uint(lamax));
    } else {
        // FINAL OUTPUT IS float32 (= bf16 values widened to f32)
        float* out = (float*)out_v;
        const float amax4 = fmaxf(g_amax[4], 1e-12f);
        const float s4 = bf16r(448.0f / amax4);       // bf16 scale
        const float f = bf16r(1.0f / s4) * g_scale_dq[3];
        #pragma unroll
        for (int mt = 0; mt < 2; mt++) {
            #pragma unroll
            for (int nt = 0; nt < 4; nt++) {
                #pragma unroll
                for (int half = 0; half < 2; half++) {
                    const int row = rbase + mt * 16 + half * 8;
                    const int col = cbase + nt * 8;
                    float2 w;
                    w.x = bf16r(accg[mt][nt][half * 2] * f);
                    w.y = bf16r(accg[mt][nt][half * 2 + 1] * f);
                    *(float2*)(out + (size_t)row * ldo + col) = w;
                }
            }
        }
    }
}

// ============================ launcher ======================================
extern "C" void kernel_launch(void* const* d_in, const int* in_sizes, int n_in,
                              void* d_out, int out_size) {
    const float* x  = (const float*)d_in[0];
    const float* gw = (const float*)d_in[1];
    const float* uw = (const float*)d_in[2];
    const float* dw = (const float*)d_in[3];

    void *p_xq, *p_gq, *p_uq, *p_dq, *p_inter, *p_iq;
    cudaGetSymbolAddress(&p_xq, g_xq);
    cudaGetSymbolAddress(&p_gq, g_gq);
    cudaGetSymbolAddress(&p_uq, g_uq);
    cudaGetSymbolAddress(&p_dq, g_dq);
    cudaGetSymbolAddress(&p_inter, g_inter);
    cudaGetSymbolAddress(&p_iq, g_iq);

    const int SMEM_FUSED = NSTAGE * 3 * TILE;  // 165888
    const int SMEM_PLAIN = NSTAGE * 2 * TILE;  // 110592
    cudaFuncSetAttribute(gemm_fp8_kernel<true>,
                         cudaFuncAttributeMaxDynamicSharedMemorySize, SMEM_FUSED);
    cudaFuncSetAttribute(gemm_fp8_kernel<false>,
                         cudaFuncAttributeMaxDynamicSharedMemorySize, SMEM_PLAIN);

    const int n4 = (T_DIM * H_DIM) / 4;  // each input tensor: 16.7M elems

    init_amax_kernel<<<1, 32>>>();
    amax_kernel<<<1024, 256>>>(x, n4, 0);
    amax_kernel<<<1024, 256>>>(gw, n4, 1);
    amax_kernel<<<1024, 256>>>(uw, n4, 2);
    amax_kernel<<<1024, 256>>>(dw, n4, 3);
    compute_scales_kernel<<<1, 32>>>();
    quant_kernel<<<2048, 256>>>(x, (unsigned char*)p_xq, n4, 0);
    quant_kernel<<<2048, 256>>>(gw, (unsigned char*)p_gq, n4, 1);
    quant_kernel<<<2048, 256>>>(uw, (unsigned char*)p_uq, n4, 2);
    quant_kernel<<<2048, 256>>>(dw, (unsigned char*)p_dq, n4, 3);

    // GEMM1 fused: inter[T, I] = gelu(xq@gq^T * sxg) * (xq@uq^T * sxu) + amax
    gemm_fp8_kernel<true><<<dim3(T_DIM / 128, I_DIM / 128), 512, SMEM_FUSED>>>(
        (const unsigned char*)p_xq, (const unsigned char*)p_gq,
        (const unsigned char*)p_uq, p_inter, H_DIM, I_DIM);

    quant_inter_kernel<<<4096, 256>>>((int)(((size_t)T_DIM * I_DIM) / 8));

    // GEMM2: out_f32[T, H] = widen_bf16((iq @ dq^T) * (i_s*d_s))
    gemm_fp8_kernel<false><<<dim3(T_DIM / 128, H_DIM / 128), 512, SMEM_PLAIN>>>(
        (const unsigned char*)p_iq, (const unsigned char*)p_dq,
        nullptr, d_out, I_DIM, H_DIM);
}

// round 14
// speedup vs baseline: 1.9410x; 1.0447x over previous
#include <cuda_runtime.h>
#include <cuda_bf16.h>
#include <cuda_fp8.h>
#include <cstdint>

// Problem dims (fixed by the dataset)
#define T_DIM 8192
#define H_DIM 2048
#define I_DIM 8192

// ============================ device scratch ================================
__device__ __align__(16) unsigned char g_xq[(size_t)T_DIM * H_DIM];
__device__ __align__(16) unsigned char g_gq[(size_t)I_DIM * H_DIM];
__device__ __align__(16) unsigned char g_uq[(size_t)I_DIM * H_DIM];
__device__ __align__(16) unsigned char g_dq[(size_t)H_DIM * I_DIM];
__device__ __align__(16) __nv_bfloat16 g_inter[(size_t)T_DIM * I_DIM];
__device__ __align__(16) unsigned char g_iq[(size_t)T_DIM * I_DIM];
__device__ float g_amax[8];      // 0:x 1:gate_w 2:up_w 3:down_w 4:inter
__device__ float g_scale_q[8];   // 448/amax
__device__ float g_scale_dq[8];  // 1/(448/amax)

// ============================ helpers =======================================
__device__ __forceinline__ uint32_t smem_u32(const void* p) {
    return (uint32_t)__cvta_generic_to_shared(p);
}

__device__ __forceinline__ void cp_async16(uint32_t saddr, const void* gptr) {
    asm volatile("cp.async.cg.shared.global [%0], [%1], 16;" :: "r"(saddr), "l"(gptr));
}
__device__ __forceinline__ void cp_async_commit() {
    asm volatile("cp.async.commit_group;" ::: "memory");
}
template <int N>
__device__ __forceinline__ void cp_async_wait() {
    asm volatile("cp.async.wait_group %0;" :: "n"(N) : "memory");
}

// volatile: must not move across barriers (reads smem filled by cp.async)
__device__ __forceinline__ void ldsm_x4(uint32_t* r, uint32_t addr) {
    asm volatile("ldmatrix.sync.aligned.m8n8.x4.shared.b16 {%0,%1,%2,%3}, [%4];"
                 : "=r"(r[0]), "=r"(r[1]), "=r"(r[2]), "=r"(r[3]) : "r"(addr));
}

// 4 packed e4m3 bytes -> two f16x2 regs (lo = bytes 0,1; hi = bytes 2,3).
__device__ __forceinline__ void cvt8(uint32_t v, uint32_t& lo, uint32_t& hi) {
    asm("{\n\t"
        ".reg .b16 l, h;\n\t"
        "mov.b32 {l, h}, %2;\n\t"
        "cvt.rn.f16x2.e4m3x2 %0, l;\n\t"
        "cvt.rn.f16x2.e4m3x2 %1, h;\n\t"
        "}"
        : "=r"(lo), "=r"(hi) : "r"(v));
}

// f16 x f16 -> f32 MMA, m16n8k16 (non-volatile: scheduler may interleave)
__device__ __forceinline__ void mma_f16(float* c, const uint32_t* a, const uint32_t* b) {
    asm("mma.sync.aligned.m16n8k16.row.col.f32.f16.f16.f32 "
        "{%0,%1,%2,%3}, {%4,%5,%6,%7}, {%8,%9}, {%0,%1,%2,%3};"
        : "+f"(c[0]), "+f"(c[1]), "+f"(c[2]), "+f"(c[3])
        : "r"(a[0]), "r"(a[1]), "r"(a[2]), "r"(a[3]), "r"(b[0]), "r"(b[1]));
}

__device__ __forceinline__ float bf16r(float x) {
    return __bfloat162float(__float2bfloat16(x));
}

// XLA's EmitFastTanh (Eigen-style rational polynomial).
__device__ __forceinline__ float xla_tanh_f32(float x) {
    const float kMax = 7.90531110763549805f;
    float xc = fminf(fmaxf(x, -kMax), kMax);
    float x2 = __fmul_rn(xc, xc);
    float np = -2.76076847742355e-16f;
    np = __fadd_rn(__fmul_rn(np, x2), 2.00018790482477e-13f);
    np = __fadd_rn(__fmul_rn(np, x2), -8.60467152213735e-11f);
    np = __fadd_rn(__fmul_rn(np, x2), 5.12229709037114e-08f);
    np = __fadd_rn(__fmul_rn(np, x2), 1.48572235717979e-05f);
    np = __fadd_rn(__fmul_rn(np, x2), 6.37261928875436e-04f);
    np = __fadd_rn(__fmul_rn(np, x2), 4.89352455891786e-03f);
    float numerator = __fmul_rn(xc, np);
    float dp = 1.19825839466702e-06f;
    dp = __fadd_rn(__fmul_rn(dp, x2), 1.18534705686654e-04f);
    dp = __fadd_rn(__fmul_rn(dp, x2), 2.26843463243900e-03f);
    dp = __fadd_rn(__fmul_rn(dp, x2), 4.89352518554385e-03f);
    float res = __fdiv_rn(numerator, dp);
    return (fabsf(x) < 0.0004f) ? x : res;
}

// Eager-mode jax.nn.gelu(approximate=True) on bf16 (per-op rounding;
// integer_pow(x,3) = two bf16-rounded multiplies).
__device__ __forceinline__ float gelu_bf16_chain(float x /* bf16-valued */) {
    float x2 = bf16r(x * x);
    float x3 = bf16r(x2 * x);
    float t1 = bf16r(0.044677734375f * x3);   // bf16(0.044715)
    float t2 = bf16r(x + t1);
    float t3 = bf16r(0.796875f * t2);         // bf16(sqrt(2/pi))
    float th = bf16r(xla_tanh_f32(t3));
    float t4 = bf16r(1.0f + th);
    float t5 = 0.5f * t4;                     // exact halving
    return bf16r(x * t5);
}

// ============================ small kernels =================================
__global__ void init_amax_kernel() {
    if (threadIdx.x < 8) g_amax[threadIdx.x] = 0.0f;
}

// One launch: amax of all four input tensors (keeps GEMM1 at launch #5).
__global__ void amax_all_kernel(const float* __restrict__ p0,
                                const float* __restrict__ p1,
                                const float* __restrict__ p2,
                                const float* __restrict__ p3, int n4) {
    const float4* ps[4] = {(const float4*)p0, (const float4*)p1,
                           (const float4*)p2, (const float4*)p3};
    #pragma unroll
    for (int t = 0; t < 4; t++) {
        const float4* s = ps[t];
        float m = 0.0f;
        for (int i = blockIdx.x * blockDim.x + threadIdx.x; i < n4;
             i += gridDim.x * blockDim.x) {
            float4 v = s[i];
            m = fmaxf(m, fmaxf(fmaxf(fabsf(v.x), fabsf(v.y)),
                               fmaxf(fabsf(v.z), fabsf(v.w))));
        }
        #pragma unroll
        for (int o = 16; o; o >>= 1)
            m = fmaxf(m, __shfl_xor_sync(0xffffffffu, m, o));
        if ((threadIdx.x & 31) == 0)
            atomicMax((unsigned int*)&g_amax[t], __float_as_uint(m));
    }
}

__global__ void compute_scales_kernel() {
    int i = threadIdx.x;
    if (i < 4) {
        float a = fmaxf(g_amax[i], 1e-12f);
        float s = 448.0f / a;
        g_scale_q[i] = s;
        g_scale_dq[i] = 1.0f / s;
    }
}

// One launch: quantize all four tensors.
__global__ void quant_all_kernel(const float* __restrict__ p0,
                                 const float* __restrict__ p1,
                                 const float* __restrict__ p2,
                                 const float* __restrict__ p3,
                                 unsigned char* __restrict__ d0,
                                 unsigned char* __restrict__ d1,
                                 unsigned char* __restrict__ d2,
                                 unsigned char* __restrict__ d3, int n4) {
    const float4* ps[4] = {(const float4*)p0, (const float4*)p1,
                           (const float4*)p2, (const float4*)p3};
    uint32_t* ds[4] = {(uint32_t*)d0, (uint32_t*)d1,
                       (uint32_t*)d2, (uint32_t*)d3};
    #pragma unroll
    for (int t = 0; t < 4; t++) {
        float s = g_scale_q[t];
        const float4* s4 = ps[t];
        uint32_t* d4 = ds[t];
        for (int i = blockIdx.x * blockDim.x + threadIdx.x; i < n4;
             i += gridDim.x * blockDim.x) {
            float4 v = s4[i];
            uint32_t b0 = __nv_cvt_float_to_fp8(v.x * s, __NV_SATFINITE, __NV_E4M3);
            uint32_t b1 = __nv_cvt_float_to_fp8(v.y * s, __NV_SATFINITE, __NV_E4M3);
            uint32_t b2 = __nv_cvt_float_to_fp8(v.z * s, __NV_SATFINITE, __NV_E4M3);
            uint32_t b3 = __nv_cvt_float_to_fp8(v.w * s, __NV_SATFINITE, __NV_E4M3);
            d4[i] = b0 | (b1 << 8) | (b2 << 16) | (b3 << 24);
        }
    }
}

// inter (bf16) -> fp8 bytes; scale chain bf16-rounded
__global__ void quant_inter_kernel(int n8) {
    float amax4 = fmaxf(g_amax[4], 1e-12f);
    float s = bf16r(448.0f / amax4);
    const uint4* src = (const uint4*)g_inter;   // 8 bf16 per uint4
    uint2* dst = (uint2*)g_iq;
    for (int i = blockIdx.x * blockDim.x + threadIdx.x; i < n8;
         i += gridDim.x * blockDim.x) {
        uint4 v = src[i];
        uint32_t words[4] = {v.x, v.y, v.z, v.w};
        uint32_t out[2] = {0u, 0u};
        #pragma unroll
        for (int w = 0; w < 4; w++) {
            float f0 = __bfloat162float(__ushort_as_bfloat16((unsigned short)(words[w] & 0xffffu)));
            float f1 = __bfloat162float(__ushort_as_bfloat16((unsigned short)(words[w] >> 16)));
            uint32_t q0 = __nv_cvt_float_to_fp8(f0 * s, __NV_SATFINITE, __NV_E4M3);
            uint32_t q1 = __nv_cvt_float_to_fp8(f1 * s, __NV_SATFINITE, __NV_E4M3);
            out[w >> 1] |= (q0 | (q1 << 8)) << ((w & 1) * 16);
        }
        dst[i] = make_uint2(out[0], out[1]);
    }
}

// ============================ GEMM kernel ===================================
// CTA tile 64(M) x 128(N), 256 threads = 8 warps (2 m x 4 n), warp tile
// 32x32, K-chunk 128 bytes, double-buffered cp.async. 2 CTAs per SM
// (independent barrier domains overlap sync/load/epilogue phases).
// fp8 bytes in smem -> exact f16 via cvt -> m16n8k16 HMMA (f32 acc).

static constexpr int KCH    = 128;              // K bytes per chunk
static constexpr int STRIDE = 144;              // padded smem row stride
static constexpr int TILE_A = 64 * STRIDE;      // 9216 B
static constexpr int TILE_B = 128 * STRIDE;     // 18432 B

template <bool FUSED>
__global__ void __launch_bounds__(256, 2)
gemm_fp8_kernel(const unsigned char* __restrict__ A,
                const unsigned char* __restrict__ B0,
                const unsigned char* __restrict__ B1,
                void* __restrict__ out_v,
                int K, int ldo) {
    extern __shared__ __align__(16) char smem[];
    const uint32_t sb = smem_u32(smem);
    const int tid = threadIdx.x;
    const int wid = tid >> 5;
    const int lid = tid & 31;
    const int warp_m = (wid & 1) * 32;
    const int warp_n = (wid >> 1) * 32;
    const int m0 = blockIdx.x * 64;
    const int n0 = blockIdx.y * 128;

    const int BUFSZ = TILE_A + (FUSED ? 2 : 1) * TILE_B;

    // A tile: 64 rows x 128 B = 512 16B-chunks; B tile: 128 rows = 1024.
    auto load_tile_a = [&](uint32_t sbase, const unsigned char* src, int k0) {
        const char* base = (const char*)src + (size_t)m0 * K + k0;
        #pragma unroll
        for (int i = 0; i < 2; i++) {
            int c = tid + i * 256;          // 0..511
            int r = c >> 3;
            int s = (c & 7) << 4;
            cp_async16(sbase + r * STRIDE + s, base + (size_t)r * K + s);
        }
    };
    auto load_tile_b = [&](uint32_t sbase, const unsigned char* src, int k0) {
        const char* base = (const char*)src + (size_t)n0 * K + k0;
        #pragma unroll
        for (int i = 0; i < 4; i++) {
            int c = tid + i * 256;          // 0..1023
            int r = c >> 3;
            int s = (c & 7) << 4;
            cp_async16(sbase + r * STRIDE + s, base + (size_t)r * K + s);
        }
    };
    auto load_chunk = [&](int buf, int kc) {
        const uint32_t s0 = sb + buf * BUFSZ;
        const int k0 = kc * KCH;
        load_tile_a(s0, A, k0);
        load_tile_b(s0 + TILE_A, B0, k0);
        if (FUSED) load_tile_b(s0 + TILE_A + TILE_B, B1, k0);
        cp_async_commit();
    };

    // ---- per-lane ldmatrix address components (validated layout) ----
    const int lr = lid & 7;
    const int lg = lid >> 3;
    const uint32_t a_lane = (uint32_t)((warp_m + lr + (lg & 1) * 8) * STRIDE +
                                       (lg >> 1) * 16);
    const uint32_t b_lane = (uint32_t)((warp_n + lr + (lg >> 1) * 8) * STRIDE +
                                       (lg & 1) * 16);

    float accg[2][4][4];
    float accu[FUSED ? 2 : 1][4][4];
    #pragma unroll
    for (int mt = 0; mt < 2; mt++)
        #pragma unroll
        for (int nt = 0; nt < 4; nt++)
            #pragma unroll
            for (int e = 0; e < 4; e++) {
                accg[mt][nt][e] = 0.0f;
                if (FUSED) accu[mt][nt][e] = 0.0f;
            }

    const int NCH = K / KCH;
    load_chunk(0, 0);

    for (int kc = 0; kc < NCH; ++kc) {
        const int buf = kc & 1;
        if (kc + 1 < NCH) {
            load_chunk(buf ^ 1, kc + 1);
            cp_async_wait<1>();
        } else {
            cp_async_wait<0>();
        }
        __syncthreads();

        const uint32_t sA  = sb + buf * BUFSZ;
        const uint32_t sBg = sA + TILE_A;
        const uint32_t sBu = sBg + TILE_B;

        #pragma unroll
        for (int ks = 0; ks < 4; ks++) {
            uint32_t af[2][4];
            #pragma unroll
            for (int mt = 0; mt < 2; mt++)
                ldsm_x4(af[mt], sA + a_lane + mt * 16 * STRIDE + ks * 32);
            uint32_t a16[2][2][4];   // [khalf][mt][4 regs]
            #pragma unroll
            for (int mt = 0; mt < 2; mt++) {
                cvt8(af[mt][0], a16[0][mt][0], a16[0][mt][2]);
                cvt8(af[mt][1], a16[0][mt][1], a16[0][mt][3]);
                cvt8(af[mt][2], a16[1][mt][0], a16[1][mt][2]);
                cvt8(af[mt][3], a16[1][mt][1], a16[1][mt][3]);
            }

            #pragma unroll
            for (int p = 0; p < 2; p++) {
                uint32_t bq[4];
                ldsm_x4(bq, sBg + b_lane + p * 16 * STRIDE + ks * 32);
                #pragma unroll
                for (int half = 0; half < 2; half++) {
                    uint32_t B0r[2], B1r[2];
                    cvt8(bq[2 * half],     B0r[0], B0r[1]);   // k 0-15
                    cvt8(bq[2 * half + 1], B1r[0], B1r[1]);   // k 16-31
                    const int nt = p * 2 + half;
                    #pragma unroll
                    for (int mt = 0; mt < 2; mt++) {
                        mma_f16(accg[mt][nt], a16[0][mt], B0r);
                        mma_f16(accg[mt][nt], a16[1][mt], B1r);
                    }
                }
            }
            if (FUSED) {
                #pragma unroll
                for (int p = 0; p < 2; p++) {
                    uint32_t bq[4];
                    ldsm_x4(bq, sBu + b_lane + p * 16 * STRIDE + ks * 32);
                    #pragma unroll
                    for (int half = 0; half < 2; half++) {
                        uint32_t B0r[2], B1r[2];
                        cvt8(bq[2 * half],     B0r[0], B0r[1]);
                        cvt8(bq[2 * half + 1], B1r[0], B1r[1]);
                        const int nt = p * 2 + half;
                        #pragma unroll
                        for (int mt = 0; mt < 2; mt++) {
                            mma_f16(accu[mt][nt], a16[0][mt], B0r);
                            mma_f16(accu[mt][nt], a16[1][mt], B1r);
                        }
                    }
                }
            }
        }
        __syncthreads();
    }

    // ---------------- epilogue ----------------
    const int rbase = m0 + warp_m + (lid >> 2);
    const int cbase = n0 + warp_n + (lid & 3) * 2;

    if (FUSED) {
        __nv_bfloat16* out = (__nv_bfloat16*)out_v;
        const float sA = g_scale_dq[0];
        const float fG = sA * g_scale_dq[1];
        const float fU = sA * g_scale_dq[2];
        float lamax = 0.0f;
        #pragma unroll
        for (int mt = 0; mt < 2; mt++) {
            #pragma unroll
            for (int nt = 0; nt < 4; nt++) {
                #pragma unroll
                for (int half = 0; half < 2; half++) {
                    const int row = rbase + mt * 16 + half * 8;
                    const int col = cbase + nt * 8;
                    uint32_t w = 0;
                    #pragma unroll
                    for (int e = 0; e < 2; e++) {
                        float gf = bf16r(accg[mt][nt][half * 2 + e] * fG);
                        float uf = bf16r(accu[mt][nt][half * 2 + e] * fU);
                        float pb = bf16r(gelu_bf16_chain(gf) * uf);
                        lamax = fmaxf(lamax, fabsf(pb));
                        w |= ((uint32_t)__bfloat16_as_ushort(__float2bfloat16(pb)))
                             << (e * 16);
                    }
                    *(uint32_t*)(out + (size_t)row * ldo + col) = w;
                }
            }
        }
        #pragma unroll
        for (int o = 16; o; o >>= 1)
            lamax = fmaxf(lamax, __shfl_xor_sync(0xffffffffu, lamax, o));
        if (lid == 0)
            atomicMax((unsigned int*)&g_amax[4], __float_as_uint(lamax));
    } else {
        // FINAL OUTPUT IS float32 (= bf16 values widened to f32)
        float* out = (float*)out_v;
        const float amax4 = fmaxf(g_amax[4], 1e-12f);
        const float s4 = bf16r(448.0f / amax4);       // bf16 scale
        const float f = bf16r(1.0f / s4) * g_scale_dq[3];
        #pragma unroll
        for (int mt = 0; mt < 2; mt++) {
            #pragma unroll
            for (int nt = 0; nt < 4; nt++) {
                #pragma unroll
                for (int half = 0; half < 2; half++) {
                    const int row = rbase + mt * 16 + half * 8;
                    const int col = cbase + nt * 8;
                    float2 w;
                    w.x = bf16r(accg[mt][nt][half * 2] * f);
                    w.y = bf16r(accg[mt][nt][half * 2 + 1] * f);
                    *(float2*)(out + (size_t)row * ldo + col) = w;
                }
            }
        }
    }
}

// ============================ launcher ======================================
extern "C" void kernel_launch(void* const* d_in, const int* in_sizes, int n_in,
                              void* d_out, int out_size) {
    const float* x  = (const float*)d_in[0];
    const float* gw = (const float*)d_in[1];
    const float* uw = (const float*)d_in[2];
    const float* dw = (const float*)d_in[3];

    void *p_xq, *p_gq, *p_uq, *p_dq, *p_inter, *p_iq;
    cudaGetSymbolAddress(&p_xq, g_xq);
    cudaGetSymbolAddress(&p_gq, g_gq);
    cudaGetSymbolAddress(&p_uq, g_uq);
    cudaGetSymbolAddress(&p_dq, g_dq);
    cudaGetSymbolAddress(&p_inter, g_inter);
    cudaGetSymbolAddress(&p_iq, g_iq);

    const int SMEM_FUSED = 2 * (TILE_A + 2 * TILE_B);  // 92160
    const int SMEM_PLAIN = 2 * (TILE_A + TILE_B);      // 55296
    cudaFuncSetAttribute(gemm_fp8_kernel<true>,
                         cudaFuncAttributeMaxDynamicSharedMemorySize, SMEM_FUSED);
    cudaFuncSetAttribute(gemm_fp8_kernel<false>,
                         cudaFuncAttributeMaxDynamicSharedMemorySize, SMEM_PLAIN);

    const int n4 = (T_DIM * H_DIM) / 4;  // each input tensor: 16.7M elems

    // Launch order matters: ncu -s 5 -c 1 captures launch #5 = GEMM1.
    init_amax_kernel<<<1, 32>>>();                                     // #1
    amax_all_kernel<<<1024, 256>>>(x, gw, uw, dw, n4);                 // #2
    compute_scales_kernel<<<1, 32>>>();                                // #3
    quant_all_kernel<<<2048, 256>>>(x, gw, uw, dw,                     // #4
        (unsigned char*)p_xq, (unsigned char*)p_gq,
        (unsigned char*)p_uq, (unsigned char*)p_dq, n4);

    // GEMM1 fused: inter[T, I] = gelu(xq@gq^T * sxg) * (xq@uq^T * sxu) + amax
    gemm_fp8_kernel<true><<<dim3(T_DIM / 64, I_DIM / 128), 256, SMEM_FUSED>>>(
        (const unsigned char*)p_xq, (const unsigned char*)p_gq,        // #5
        (const unsigned char*)p_uq, p_inter, H_DIM, I_DIM);

    quant_inter_kernel<<<4096, 256>>>((int)(((size_t)T_DIM * I_DIM) / 8)); // #6

    // GEMM2: out_f32[T, H] = widen_bf16((iq @ dq^T) * (i_s*d_s))
    gemm_fp8_kernel<false><<<dim3(T_DIM / 64, H_DIM / 128), 256, SMEM_PLAIN>>>(
        (const unsigned char*)p_iq, (const unsigned char*)p_dq,        // #7
        nullptr, d_out, I_DIM, H_DIM);
}

// round 15
// speedup vs baseline: 1.9600x; 1.0098x over previous
#include <cuda_runtime.h>
#include <cuda_bf16.h>
#include <cuda_fp8.h>
#include <cstdint>

// Problem dims (fixed by the dataset)
#define T_DIM 8192
#define H_DIM 2048
#define I_DIM 8192

// ============================ device scratch ================================
__device__ __align__(16) unsigned char g_xq[(size_t)T_DIM * H_DIM];
__device__ __align__(16) unsigned char g_gq[(size_t)I_DIM * H_DIM];
__device__ __align__(16) unsigned char g_uq[(size_t)I_DIM * H_DIM];
__device__ __align__(16) unsigned char g_dq[(size_t)H_DIM * I_DIM];
__device__ __align__(16) __nv_bfloat16 g_inter[(size_t)T_DIM * I_DIM];
__device__ __align__(16) unsigned char g_iq[(size_t)T_DIM * I_DIM];
__device__ float g_amax[8];      // 0:x 1:gate_w 2:up_w 3:down_w 4:inter
__device__ float g_scale_q[8];   // 448/amax
__device__ float g_scale_dq[8];  // 1/(448/amax)

// ============================ helpers =======================================
__device__ __forceinline__ uint32_t smem_u32(const void* p) {
    return (uint32_t)__cvta_generic_to_shared(p);
}

__device__ __forceinline__ void cp_async16(uint32_t saddr, const void* gptr) {
    asm volatile("cp.async.cg.shared.global [%0], [%1], 16;" :: "r"(saddr), "l"(gptr));
}
__device__ __forceinline__ void cp_async_commit() {
    asm volatile("cp.async.commit_group;" ::: "memory");
}
template <int N>
__device__ __forceinline__ void cp_async_wait() {
    asm volatile("cp.async.wait_group %0;" :: "n"(N) : "memory");
}

// volatile: must not move across barriers (reads smem filled by cp.async)
__device__ __forceinline__ void ldsm_x4(uint32_t* r, uint32_t addr) {
    asm volatile("ldmatrix.sync.aligned.m8n8.x4.shared.b16 {%0,%1,%2,%3}, [%4];"
                 : "=r"(r[0]), "=r"(r[1]), "=r"(r[2]), "=r"(r[3]) : "r"(addr));
}

// 4 packed e4m3 bytes -> two f16x2 regs (lo = bytes 0,1; hi = bytes 2,3).
__device__ __forceinline__ void cvt8(uint32_t v, uint32_t& lo, uint32_t& hi) {
    asm("{\n\t"
        ".reg .b16 l, h;\n\t"
        "mov.b32 {l, h}, %2;\n\t"
        "cvt.rn.f16x2.e4m3x2 %0, l;\n\t"
        "cvt.rn.f16x2.e4m3x2 %1, h;\n\t"
        "}"
        : "=r"(lo), "=r"(hi) : "r"(v));
}

// f16 x f16 -> f32 MMA, m16n8k16 (non-volatile: scheduler may interleave)
__device__ __forceinline__ void mma_f16(float* c, const uint32_t* a, const uint32_t* b) {
    asm("mma.sync.aligned.m16n8k16.row.col.f32.f16.f16.f32 "
        "{%0,%1,%2,%3}, {%4,%5,%6,%7}, {%8,%9}, {%0,%1,%2,%3};"
        : "+f"(c[0]), "+f"(c[1]), "+f"(c[2]), "+f"(c[3])
        : "r"(a[0]), "r"(a[1]), "r"(a[2]), "r"(a[3]), "r"(b[0]), "r"(b[1]));
}

__device__ __forceinline__ float bf16r(float x) {
    return __bfloat162float(__float2bfloat16(x));
}

// XLA's EmitFastTanh (Eigen-style rational polynomial).
__device__ __forceinline__ float xla_tanh_f32(float x) {
    const float kMax = 7.90531110763549805f;
    float xc = fminf(fmaxf(x, -kMax), kMax);
    float x2 = __fmul_rn(xc, xc);
    float np = -2.76076847742355e-16f;
    np = __fadd_rn(__fmul_rn(np, x2), 2.00018790482477e-13f);
    np = __fadd_rn(__fmul_rn(np, x2), -8.60467152213735e-11f);
    np = __fadd_rn(__fmul_rn(np, x2), 5.12229709037114e-08f);
    np = __fadd_rn(__fmul_rn(np, x2), 1.48572235717979e-05f);
    np = __fadd_rn(__fmul_rn(np, x2), 6.37261928875436e-04f);
    np = __fadd_rn(__fmul_rn(np, x2), 4.89352455891786e-03f);
    float numerator = __fmul_rn(xc, np);
    float dp = 1.19825839466702e-06f;
    dp = __fadd_rn(__fmul_rn(dp, x2), 1.18534705686654e-04f);
    dp = __fadd_rn(__fmul_rn(dp, x2), 2.26843463243900e-03f);
    dp = __fadd_rn(__fmul_rn(dp, x2), 4.89352518554385e-03f);
    float res = __fdiv_rn(numerator, dp);
    return (fabsf(x) < 0.0004f) ? x : res;
}

// Eager-mode jax.nn.gelu(approximate=True) on bf16 (per-op rounding;
// integer_pow(x,3) = two bf16-rounded multiplies).
__device__ __forceinline__ float gelu_bf16_chain(float x /* bf16-valued */) {
    float x2 = bf16r(x * x);
    float x3 = bf16r(x2 * x);
    float t1 = bf16r(0.044677734375f * x3);   // bf16(0.044715)
    float t2 = bf16r(x + t1);
    float t3 = bf16r(0.796875f * t2);         // bf16(sqrt(2/pi))
    float th = bf16r(xla_tanh_f32(t3));
    float t4 = bf16r(1.0f + th);
    float t5 = 0.5f * t4;                     // exact halving
    return bf16r(x * t5);
}

// ============================ small kernels =================================
__global__ void init_amax_kernel() {
    if (threadIdx.x < 8) g_amax[threadIdx.x] = 0.0f;
}

// Parallel across tensors: blockIdx.x & 3 selects tensor; all four streamed
// concurrently (one DRAM-saturating pass instead of four sequential ones).
__global__ void amax_all_kernel(const float* __restrict__ p0,
                                const float* __restrict__ p1,
                                const float* __restrict__ p2,
                                const float* __restrict__ p3, int n4) {
    const float4* ps[4] = {(const float4*)p0, (const float4*)p1,
                           (const float4*)p2, (const float4*)p3};
    const int t = blockIdx.x & 3;
    const int bid = blockIdx.x >> 2;
    const int nb = gridDim.x >> 2;
    const float4* s = ps[t];
    float m = 0.0f;
    for (int i = bid * blockDim.x + threadIdx.x; i < n4; i += nb * blockDim.x) {
        float4 v = s[i];
        m = fmaxf(m, fmaxf(fmaxf(fabsf(v.x), fabsf(v.y)),
                           fmaxf(fabsf(v.z), fabsf(v.w))));
    }
    #pragma unroll
    for (int o = 16; o; o >>= 1)
        m = fmaxf(m, __shfl_xor_sync(0xffffffffu, m, o));
    if ((threadIdx.x & 31) == 0)
        atomicMax((unsigned int*)&g_amax[t], __float_as_uint(m));
}

__global__ void compute_scales_kernel() {
    int i = threadIdx.x;
    if (i < 4) {
        float a = fmaxf(g_amax[i], 1e-12f);
        float s = 448.0f / a;
        g_scale_q[i] = s;
        g_scale_dq[i] = 1.0f / s;
    }
}

// Parallel across tensors, same scheme.
__global__ void quant_all_kernel(const float* __restrict__ p0,
                                 const float* __restrict__ p1,
                                 const float* __restrict__ p2,
                                 const float* __restrict__ p3,
                                 unsigned char* __restrict__ d0,
                                 unsigned char* __restrict__ d1,
                                 unsigned char* __restrict__ d2,
                                 unsigned char* __restrict__ d3, int n4) {
    const float4* ps[4] = {(const float4*)p0, (const float4*)p1,
                           (const float4*)p2, (const float4*)p3};
    uint32_t* ds[4] = {(uint32_t*)d0, (uint32_t*)d1,
                       (uint32_t*)d2, (uint32_t*)d3};
    const int t = blockIdx.x & 3;
    const int bid = blockIdx.x >> 2;
    const int nb = gridDim.x >> 2;
    float s = g_scale_q[t];
    const float4* s4 = ps[t];
    uint32_t* d4 = ds[t];
    for (int i = bid * blockDim.x + threadIdx.x; i < n4; i += nb * blockDim.x) {
        float4 v = s4[i];
        uint32_t b0 = __nv_cvt_float_to_fp8(v.x * s, __NV_SATFINITE, __NV_E4M3);
        uint32_t b1 = __nv_cvt_float_to_fp8(v.y * s, __NV_SATFINITE, __NV_E4M3);
        uint32_t b2 = __nv_cvt_float_to_fp8(v.z * s, __NV_SATFINITE, __NV_E4M3);
        uint32_t b3 = __nv_cvt_float_to_fp8(v.w * s, __NV_SATFINITE, __NV_E4M3);
        d4[i] = b0 | (b1 << 8) | (b2 << 16) | (b3 << 24);
    }
}

// inter (bf16) -> fp8 bytes; scale chain bf16-rounded
__global__ void quant_inter_kernel(int n8) {
    float amax4 = fmaxf(g_amax[4], 1e-12f);
    float s = bf16r(448.0f / amax4);
    const uint4* src = (const uint4*)g_inter;   // 8 bf16 per uint4
    uint2* dst = (uint2*)g_iq;
    for (int i = blockIdx.x * blockDim.x + threadIdx.x; i < n8;
         i += gridDim.x * blockDim.x) {
        uint4 v = src[i];
        uint32_t words[4] = {v.x, v.y, v.z, v.w};
        uint32_t out[2] = {0u, 0u};
        #pragma unroll
        for (int w = 0; w < 4; w++) {
            float f0 = __bfloat162float(__ushort_as_bfloat16((unsigned short)(words[w] & 0xffffu)));
            float f1 = __bfloat162float(__ushort_as_bfloat16((unsigned short)(words[w] >> 16)));
            uint32_t q0 = __nv_cvt_float_to_fp8(f0 * s, __NV_SATFINITE, __NV_E4M3);
            uint32_t q1 = __nv_cvt_float_to_fp8(f1 * s, __NV_SATFINITE, __NV_E4M3);
            out[w >> 1] |= (q0 | (q1 << 8)) << ((w & 1) * 16);
        }
        dst[i] = make_uint2(out[0], out[1]);
    }
}

// ============================ GEMM kernel ===================================
// CTA tile 64(M) x 128(N), 256 threads = 8 warps (2 m x 4 n), warp tile
// 32x32, K-chunk 128 bytes, double-buffered cp.async, 2 CTAs per SM.
// fp8 bytes in smem -> exact f16 via cvt -> m16n8k16 HMMA (f32 acc).
// Per ks-step: ALL ldsm issued back-to-back (max MLP), then cvt + mma.

static constexpr int KCH    = 128;              // K bytes per chunk
static constexpr int STRIDE = 144;              // padded smem row stride
static constexpr int TILE_A = 64 * STRIDE;      // 9216 B
static constexpr int TILE_B = 128 * STRIDE;     // 18432 B

template <bool FUSED>
__global__ void __launch_bounds__(256, 2)
gemm_fp8_kernel(const unsigned char* __restrict__ A,
                const unsigned char* __restrict__ B0,
                const unsigned char* __restrict__ B1,
                void* __restrict__ out_v,
                int K, int ldo) {
    extern __shared__ __align__(16) char smem[];
    const uint32_t sb = smem_u32(smem);
    const int tid = threadIdx.x;
    const int wid = tid >> 5;
    const int lid = tid & 31;
    const int warp_m = (wid & 1) * 32;
    const int warp_n = (wid >> 1) * 32;
    const int m0 = blockIdx.x * 64;
    const int n0 = blockIdx.y * 128;

    const int BUFSZ = TILE_A + (FUSED ? 2 : 1) * TILE_B;

    auto load_tile_a = [&](uint32_t sbase, const unsigned char* src, int k0) {
        const char* base = (const char*)src + (size_t)m0 * K + k0;
        #pragma unroll
        for (int i = 0; i < 2; i++) {
            int c = tid + i * 256;          // 0..511
            int r = c >> 3;
            int s = (c & 7) << 4;
            cp_async16(sbase + r * STRIDE + s, base + (size_t)r * K + s);
        }
    };
    auto load_tile_b = [&](uint32_t sbase, const unsigned char* src, int k0) {
        const char* base = (const char*)src + (size_t)n0 * K + k0;
        #pragma unroll
        for (int i = 0; i < 4; i++) {
            int c = tid + i * 256;          // 0..1023
            int r = c >> 3;
            int s = (c & 7) << 4;
            cp_async16(sbase + r * STRIDE + s, base + (size_t)r * K + s);
        }
    };
    auto load_chunk = [&](int buf, int kc) {
        const uint32_t s0 = sb + buf * BUFSZ;
        const int k0 = kc * KCH;
        load_tile_a(s0, A, k0);
        load_tile_b(s0 + TILE_A, B0, k0);
        if (FUSED) load_tile_b(s0 + TILE_A + TILE_B, B1, k0);
        cp_async_commit();
    };

    // ---- per-lane ldmatrix address components (validated layout) ----
    const int lr = lid & 7;
    const int lg = lid >> 3;
    const uint32_t a_lane = (uint32_t)((warp_m + lr + (lg & 1) * 8) * STRIDE +
                                       (lg >> 1) * 16);
    const uint32_t b_lane = (uint32_t)((warp_n + lr + (lg >> 1) * 8) * STRIDE +
                                       (lg & 1) * 16);

    float accg[2][4][4];
    float accu[FUSED ? 2 : 1][4][4];
    #pragma unroll
    for (int mt = 0; mt < 2; mt++)
        #pragma unroll
        for (int nt = 0; nt < 4; nt++)
            #pragma unroll
            for (int e = 0; e < 4; e++) {
                accg[mt][nt][e] = 0.0f;
                if (FUSED) accu[mt][nt][e] = 0.0f;
            }

    const int NCH = K / KCH;
    load_chunk(0, 0);

    for (int kc = 0; kc < NCH; ++kc) {
        const int buf = kc & 1;
        if (kc + 1 < NCH) {
            load_chunk(buf ^ 1, kc + 1);
            cp_async_wait<1>();
        } else {
            cp_async_wait<0>();
        }
        __syncthreads();

        const uint32_t sA  = sb + buf * BUFSZ;
        const uint32_t sBg = sA + TILE_A;
        const uint32_t sBu = sBg + TILE_B;

        #pragma unroll
        for (int ks = 0; ks < 4; ks++) {
            const uint32_t ko = ks * 32;
            // ---- batch ALL ldsm of this step (max memory-level parallelism)
            uint32_t af[2][4], bgq[2][4], buq[2][4];
            ldsm_x4(af[0], sA + a_lane + ko);
            ldsm_x4(af[1], sA + a_lane + 16 * STRIDE + ko);
            ldsm_x4(bgq[0], sBg + b_lane + ko);
            ldsm_x4(bgq[1], sBg + b_lane + 16 * STRIDE + ko);
            if (FUSED) {
                ldsm_x4(buq[0], sBu + b_lane + ko);
                ldsm_x4(buq[1], sBu + b_lane + 16 * STRIDE + ko);
            }

            // ---- convert A
            uint32_t a16[2][2][4];   // [khalf][mt][4 regs]
            #pragma unroll
            for (int mt = 0; mt < 2; mt++) {
                cvt8(af[mt][0], a16[0][mt][0], a16[0][mt][2]);
                cvt8(af[mt][1], a16[0][mt][1], a16[0][mt][3]);
                cvt8(af[mt][2], a16[1][mt][0], a16[1][mt][2]);
                cvt8(af[mt][3], a16[1][mt][1], a16[1][mt][3]);
            }

            // ---- gate tensor: convert + mma
            #pragma unroll
            for (int p = 0; p < 2; p++) {
                #pragma unroll
                for (int half = 0; half < 2; half++) {
                    uint32_t B0r[2], B1r[2];
                    cvt8(bgq[p][2 * half],     B0r[0], B0r[1]);   // k 0-15
                    cvt8(bgq[p][2 * half + 1], B1r[0], B1r[1]);   // k 16-31
                    const int nt = p * 2 + half;
                    #pragma unroll
                    for (int mt = 0; mt < 2; mt++) {
                        mma_f16(accg[mt][nt], a16[0][mt], B0r);
                        mma_f16(accg[mt][nt], a16[1][mt], B1r);
                    }
                }
            }
            if (FUSED) {
                #pragma unroll
                for (int p = 0; p < 2; p++) {
                    #pragma unroll
                    for (int half = 0; half < 2; half++) {
                        uint32_t B0r[2], B1r[2];
                        cvt8(buq[p][2 * half],     B0r[0], B0r[1]);
                        cvt8(buq[p][2 * half + 1], B1r[0], B1r[1]);
                        const int nt = p * 2 + half;
                        #pragma unroll
                        for (int mt = 0; mt < 2; mt++) {
                            mma_f16(accu[mt][nt], a16[0][mt], B0r);
                            mma_f16(accu[mt][nt], a16[1][mt], B1r);
                        }
                    }
                }
            }
        }
        __syncthreads();
    }

    // ---------------- epilogue ----------------
    const int rbase = m0 + warp_m + (lid >> 2);
    const int cbase = n0 + warp_n + (lid & 3) * 2;

    if (FUSED) {
        __nv_bfloat16* out = (__nv_bfloat16*)out_v;
        const float sA = g_scale_dq[0];
        const float fG = sA * g_scale_dq[1];
        const float fU = sA * g_scale_dq[2];
        float lamax = 0.0f;
        #pragma unroll
        for (int mt = 0; mt < 2; mt++) {
            #pragma unroll
            for (int nt = 0; nt < 4; nt++) {
                #pragma unroll
                for (int half = 0; half < 2; half++) {
                    const int row = rbase + mt * 16 + half * 8;
                    const int col = cbase + nt * 8;
                    uint32_t w = 0;
                    #pragma unroll
                    for (int e = 0; e < 2; e++) {
                        float gf = bf16r(accg[mt][nt][half * 2 + e] * fG);
                        float uf = bf16r(accu[mt][nt][half * 2 + e] * fU);
                        float pb = bf16r(gelu_bf16_chain(gf) * uf);
                        lamax = fmaxf(lamax, fabsf(pb));
                        w |= ((uint32_t)__bfloat16_as_ushort(__float2bfloat16(pb)))
                             << (e * 16);
                    }
                    *(uint32_t*)(out + (size_t)row * ldo + col) = w;
                }
            }
        }
        #pragma unroll
        for (int o = 16; o; o >>= 1)
            lamax = fmaxf(lamax, __shfl_xor_sync(0xffffffffu, lamax, o));
        if (lid == 0)
            atomicMax((unsigned int*)&g_amax[4], __float_as_uint(lamax));
    } else {
        // FINAL OUTPUT IS float32 (= bf16 values widened to f32)
        float* out = (float*)out_v;
        const float amax4 = fmaxf(g_amax[4], 1e-12f);
        const float s4 = bf16r(448.0f / amax4);       // bf16 scale
        const float f = bf16r(1.0f / s4) * g_scale_dq[3];
        #pragma unroll
        for (int mt = 0; mt < 2; mt++) {
            #pragma unroll
            for (int nt = 0; nt < 4; nt++) {
                #pragma unroll
                for (int half = 0; half < 2; half++) {
                    const int row = rbase + mt * 16 + half * 8;
                    const int col = cbase + nt * 8;
                    float2 w;
                    w.x = bf16r(accg[mt][nt][half * 2] * f);
                    w.y = bf16r(accg[mt][nt][half * 2 + 1] * f);
                    *(float2*)(out + (size_t)row * ldo + col) = w;
                }
            }
        }
    }
}

// ============================ launcher ======================================
extern "C" void kernel_launch(void* const* d_in, const int* in_sizes, int n_in,
                              void* d_out, int out_size) {
    const float* x  = (const float*)d_in[0];
    const float* gw = (const float*)d_in[1];
    const float* uw = (const float*)d_in[2];
    const float* dw = (const float*)d_in[3];

    void *p_xq, *p_gq, *p_uq, *p_dq, *p_inter, *p_iq;
    cudaGetSymbolAddress(&p_xq, g_xq);
    cudaGetSymbolAddress(&p_gq, g_gq);
    cudaGetSymbolAddress(&p_uq, g_uq);
    cudaGetSymbolAddress(&p_dq, g_dq);
    cudaGetSymbolAddress(&p_inter, g_inter);
    cudaGetSymbolAddress(&p_iq, g_iq);

    const int SMEM_FUSED = 2 * (TILE_A + 2 * TILE_B);  // 92160
    const int SMEM_PLAIN = 2 * (TILE_A + TILE_B);      // 55296
    cudaFuncSetAttribute(gemm_fp8_kernel<true>,
                         cudaFuncAttributeMaxDynamicSharedMemorySize, SMEM_FUSED);
    cudaFuncSetAttribute(gemm_fp8_kernel<false>,
                         cudaFuncAttributeMaxDynamicSharedMemorySize, SMEM_PLAIN);

    const int n4 = (T_DIM * H_DIM) / 4;  // each input tensor: 16.7M elems

    // Launch order: ncu -s 5 -c 1 captures launch #5 = GEMM1.
    init_amax_kernel<<<1, 32>>>();                                     // #1
    amax_all_kernel<<<4096, 256>>>(x, gw, uw, dw, n4);                 // #2
    compute_scales_kernel<<<1, 32>>>();                                // #3
    quant_all_kernel<<<8192, 256>>>(x, gw, uw, dw,                     // #4
        (unsigned char*)p_xq, (unsigned char*)p_gq,
        (unsigned char*)p_uq, (unsigned char*)p_dq, n4);

    // GEMM1 fused: inter[T, I] = gelu(xq@gq^T * sxg) * (xq@uq^T * sxu) + amax
    gemm_fp8_kernel<true><<<dim3(T_DIM / 64, I_DIM / 128), 256, SMEM_FUSED>>>(
        (const unsigned char*)p_xq, (const unsigned char*)p_gq,        // #5
        (const unsigned char*)p_uq, p_inter, H_DIM, I_DIM);

    quant_inter_kernel<<<4096, 256>>>((int)(((size_t)T_DIM * I_DIM) / 8)); // #6

    // GEMM2: out_f32[T, H] = widen_bf16((iq @ dq^T) * (i_s*d_s))
    gemm_fp8_kernel<false><<<dim3(T_DIM / 64, H_DIM / 128), 256, SMEM_PLAIN>>>(
        (const unsigned char*)p_iq, (const unsigned char*)p_dq,        // #7
        nullptr, d_out, I_DIM, H_DIM);
}

// round 16
// speedup vs baseline: 2.0704x; 1.0563x over previous
#include <cuda_runtime.h>
#include <cuda_bf16.h>
#include <cuda_fp8.h>
#include <cstdint>

// Problem dims (fixed by the dataset)
#define T_DIM 8192
#define H_DIM 2048
#define I_DIM 8192

// ============================ device scratch ================================
__device__ __align__(16) unsigned char g_xq[(size_t)T_DIM * H_DIM];
__device__ __align__(16) unsigned char g_gq[(size_t)I_DIM * H_DIM];
__device__ __align__(16) unsigned char g_uq[(size_t)I_DIM * H_DIM];
__device__ __align__(16) unsigned char g_dq[(size_t)H_DIM * I_DIM];
__device__ __align__(16) __nv_bfloat16 g_inter[(size_t)T_DIM * I_DIM];
__device__ __align__(16) unsigned char g_iq[(size_t)T_DIM * I_DIM];
__device__ float g_amax[8];      // 0:x 1:gate_w 2:up_w 3:down_w 4:inter
__device__ float g_scale_q[8];   // 448/amax
__device__ float g_scale_dq[8];  // 1/(448/amax)
// h(x) = bf16(0.5*(1+tanh_chain(x))) for every bf16 bit pattern x.
__device__ __align__(16) unsigned short g_gelu_lut[65536];

// ============================ helpers =======================================
__device__ __forceinline__ uint32_t smem_u32(const void* p) {
    return (uint32_t)__cvta_generic_to_shared(p);
}

__device__ __forceinline__ void cp_async16(uint32_t saddr, const void* gptr) {
    asm volatile("cp.async.cg.shared.global [%0], [%1], 16;" :: "r"(saddr), "l"(gptr));
}
__device__ __forceinline__ void cp_async_commit() {
    asm volatile("cp.async.commit_group;" ::: "memory");
}
template <int N>
__device__ __forceinline__ void cp_async_wait() {
    asm volatile("cp.async.wait_group %0;" :: "n"(N) : "memory");
}

// volatile: must not move across barriers (reads smem filled by cp.async)
__device__ __forceinline__ void ldsm_x4(uint32_t* r, uint32_t addr) {
    asm volatile("ldmatrix.sync.aligned.m8n8.x4.shared.b16 {%0,%1,%2,%3}, [%4];"
                 : "=r"(r[0]), "=r"(r[1]), "=r"(r[2]), "=r"(r[3]) : "r"(addr));
}

// 4 packed e4m3 bytes -> two f16x2 regs (lo = bytes 0,1; hi = bytes 2,3).
__device__ __forceinline__ void cvt8(uint32_t v, uint32_t& lo, uint32_t& hi) {
    asm("{\n\t"
        ".reg .b16 l, h;\n\t"
        "mov.b32 {l, h}, %2;\n\t"
        "cvt.rn.f16x2.e4m3x2 %0, l;\n\t"
        "cvt.rn.f16x2.e4m3x2 %1, h;\n\t"
        "}"
        : "=r"(lo), "=r"(hi) : "r"(v));
}

// f16 x f16 -> f32 MMA, m16n8k16 (non-volatile: scheduler may interleave)
__device__ __forceinline__ void mma_f16(float* c, const uint32_t* a, const uint32_t* b) {
    asm("mma.sync.aligned.m16n8k16.row.col.f32.f16.f16.f32 "
        "{%0,%1,%2,%3}, {%4,%5,%6,%7}, {%8,%9}, {%0,%1,%2,%3};"
        : "+f"(c[0]), "+f"(c[1]), "+f"(c[2]), "+f"(c[3])
        : "r"(a[0]), "r"(a[1]), "r"(a[2]), "r"(a[3]), "r"(b[0]), "r"(b[1]));
}

__device__ __forceinline__ float bf16r(float x) {
    return __bfloat162float(__float2bfloat16(x));
}

// XLA's EmitFastTanh (Eigen-style rational polynomial).
__device__ __forceinline__ float xla_tanh_f32(float x) {
    const float kMax = 7.90531110763549805f;
    float xc = fminf(fmaxf(x, -kMax), kMax);
    float x2 = __fmul_rn(xc, xc);
    float np = -2.76076847742355e-16f;
    np = __fadd_rn(__fmul_rn(np, x2), 2.00018790482477e-13f);
    np = __fadd_rn(__fmul_rn(np, x2), -8.60467152213735e-11f);
    np = __fadd_rn(__fmul_rn(np, x2), 5.12229709037114e-08f);
    np = __fadd_rn(__fmul_rn(np, x2), 1.48572235717979e-05f);
    np = __fadd_rn(__fmul_rn(np, x2), 6.37261928875436e-04f);
    np = __fadd_rn(__fmul_rn(np, x2), 4.89352455891786e-03f);
    float numerator = __fmul_rn(xc, np);
    float dp = 1.19825839466702e-06f;
    dp = __fadd_rn(__fmul_rn(dp, x2), 1.18534705686654e-04f);
    dp = __fadd_rn(__fmul_rn(dp, x2), 2.26843463243900e-03f);
    dp = __fadd_rn(__fmul_rn(dp, x2), 4.89352518554385e-03f);
    float res = __fdiv_rn(numerator, dp);
    return (fabsf(x) < 0.0004f) ? x : res;
}

// ============================ small kernels =================================
__global__ void init_amax_kernel() {
    if (threadIdx.x < 8) g_amax[threadIdx.x] = 0.0f;
}

// Precompute h(x) for gelu: x is a bf16 bit pattern. Full eager-mode chain:
// x2=bf16(x*x); x3=bf16(x2*x); t1=bf16(c1*x3); t2=bf16(x+t1); t3=bf16(c2*t2);
// th=bf16(tanh(t3)); t4=bf16(1+th); t5=0.5*t4 (exact). gelu(x)=bf16(x*t5).
__global__ void gelu_lut_init_kernel() {
    int i = blockIdx.x * blockDim.x + threadIdx.x;   // 0..65535
    float x = __bfloat162float(__ushort_as_bfloat16((unsigned short)i));
    float x2 = bf16r(x * x);
    float x3 = bf16r(x2 * x);
    float t1 = bf16r(0.044677734375f * x3);
    float t2 = bf16r(x + t1);
    float t3 = bf16r(0.796875f * t2);
    float th = bf16r(xla_tanh_f32(t3));
    float t4 = bf16r(1.0f + th);
    float t5 = 0.5f * t4;                     // exactly representable in bf16
    g_gelu_lut[i] = __bfloat16_as_ushort(__float2bfloat16(t5));
}

// Parallel across tensors (measured faster for amax).
__global__ void amax_all_kernel(const float* __restrict__ p0,
                                const float* __restrict__ p1,
                                const float* __restrict__ p2,
                                const float* __restrict__ p3, int n4) {
    const float4* ps[4] = {(const float4*)p0, (const float4*)p1,
                           (const float4*)p2, (const float4*)p3};
    const int t = blockIdx.x & 3;
    const int bid = blockIdx.x >> 2;
    const int nb = gridDim.x >> 2;
    const float4* s = ps[t];
    float m = 0.0f;
    for (int i = bid * blockDim.x + threadIdx.x; i < n4; i += nb * blockDim.x) {
        float4 v = s[i];
        m = fmaxf(m, fmaxf(fmaxf(fabsf(v.x), fabsf(v.y)),
                           fmaxf(fabsf(v.z), fabsf(v.w))));
    }
    #pragma unroll
    for (int o = 16; o; o >>= 1)
        m = fmaxf(m, __shfl_xor_sync(0xffffffffu, m, o));
    if ((threadIdx.x & 31) == 0)
        atomicMax((unsigned int*)&g_amax[t], __float_as_uint(m));
}

__global__ void compute_scales_kernel() {
    int i = threadIdx.x;
    if (i < 4) {
        float a = fmaxf(g_amax[i], 1e-12f);
        float s = 448.0f / a;
        g_scale_q[i] = s;
        g_scale_dq[i] = 1.0f / s;
    }
}

// Sequential over tensors (measured faster than tensor-parallel for quant).
__global__ void quant_all_kernel(const float* __restrict__ p0,
                                 const float* __restrict__ p1,
                                 const float* __restrict__ p2,
                                 const float* __restrict__ p3,
                                 unsigned char* __restrict__ d0,
                                 unsigned char* __restrict__ d1,
                                 unsigned char* __restrict__ d2,
                                 unsigned char* __restrict__ d3, int n4) {
    const float4* ps[4] = {(const float4*)p0, (const float4*)p1,
                           (const float4*)p2, (const float4*)p3};
    uint32_t* ds[4] = {(uint32_t*)d0, (uint32_t*)d1,
                       (uint32_t*)d2, (uint32_t*)d3};
    #pragma unroll
    for (int t = 0; t < 4; t++) {
        float s = g_scale_q[t];
        const float4* s4 = ps[t];
        uint32_t* d4 = ds[t];
        for (int i = blockIdx.x * blockDim.x + threadIdx.x; i < n4;
             i += gridDim.x * blockDim.x) {
            float4 v = s4[i];
            uint32_t b0 = __nv_cvt_float_to_fp8(v.x * s, __NV_SATFINITE, __NV_E4M3);
            uint32_t b1 = __nv_cvt_float_to_fp8(v.y * s, __NV_SATFINITE, __NV_E4M3);
            uint32_t b2 = __nv_cvt_float_to_fp8(v.z * s, __NV_SATFINITE, __NV_E4M3);
            uint32_t b3 = __nv_cvt_float_to_fp8(v.w * s, __NV_SATFINITE, __NV_E4M3);
            d4[i] = b0 | (b1 << 8) | (b2 << 16) | (b3 << 24);
        }
    }
}

// inter (bf16) -> fp8 bytes; scale chain bf16-rounded
__global__ void quant_inter_kernel(int n8) {
    float amax4 = fmaxf(g_amax[4], 1e-12f);
    float s = bf16r(448.0f / amax4);
    const uint4* src = (const uint4*)g_inter;   // 8 bf16 per uint4
    uint2* dst = (uint2*)g_iq;
    for (int i = blockIdx.x * blockDim.x + threadIdx.x; i < n8;
         i += gridDim.x * blockDim.x) {
        uint4 v = src[i];
        uint32_t words[4] = {v.x, v.y, v.z, v.w};
        uint32_t out[2] = {0u, 0u};
        #pragma unroll
        for (int w = 0; w < 4; w++) {
            float f0 = __bfloat162float(__ushort_as_bfloat16((unsigned short)(words[w] & 0xffffu)));
            float f1 = __bfloat162float(__ushort_as_bfloat16((unsigned short)(words[w] >> 16)));
            uint32_t q0 = __nv_cvt_float_to_fp8(f0 * s, __NV_SATFINITE, __NV_E4M3);
            uint32_t q1 = __nv_cvt_float_to_fp8(f1 * s, __NV_SATFINITE, __NV_E4M3);
            out[w >> 1] |= (q0 | (q1 << 8)) << ((w & 1) * 16);
        }
        dst[i] = make_uint2(out[0], out[1]);
    }
}

// ============================ GEMM kernel ===================================
// CTA tile 64(M) x 128(N), 256 threads = 8 warps (2 m x 4 n), warp tile
// 32x32, K-chunk 128 bytes, 2 CTAs per SM. fp8 bytes in smem -> exact f16
// via cvt -> m16n8k16 HMMA (f32 acc). NSTAGE=2 (fused) / 3 (plain).
// FUSED epilogue: LUT-based bit-exact gelu.

static constexpr int KCH    = 128;              // K bytes per chunk
static constexpr int STRIDE = 144;              // padded smem row stride
static constexpr int TILE_A = 64 * STRIDE;      // 9216 B
static constexpr int TILE_B = 128 * STRIDE;     // 18432 B

template <bool FUSED, int NSTAGE>
__global__ void __launch_bounds__(256, 2)
gemm_fp8_kernel(const unsigned char* __restrict__ A,
                const unsigned char* __restrict__ B0,
                const unsigned char* __restrict__ B1,
                void* __restrict__ out_v,
                int K, int ldo) {
    extern __shared__ __align__(16) char smem[];
    const uint32_t sb = smem_u32(smem);
    const int tid = threadIdx.x;
    const int wid = tid >> 5;
    const int lid = tid & 31;
    const int warp_m = (wid & 1) * 32;
    const int warp_n = (wid >> 1) * 32;
    const int m0 = blockIdx.x * 64;
    const int n0 = blockIdx.y * 128;

    const int BUFSZ = TILE_A + (FUSED ? 2 : 1) * TILE_B;

    auto load_tile_a = [&](uint32_t sbase, const unsigned char* src, int k0) {
        const char* base = (const char*)src + (size_t)m0 * K + k0;
        #pragma unroll
        for (int i = 0; i < 2; i++) {
            int c = tid + i * 256;          // 0..511
            int r = c >> 3;
            int s = (c & 7) << 4;
            cp_async16(sbase + r * STRIDE + s, base + (size_t)r * K + s);
        }
    };
    auto load_tile_b = [&](uint32_t sbase, const unsigned char* src, int k0) {
        const char* base = (const char*)src + (size_t)n0 * K + k0;
        #pragma unroll
        for (int i = 0; i < 4; i++) {
            int c = tid + i * 256;          // 0..1023
            int r = c >> 3;
            int s = (c & 7) << 4;
            cp_async16(sbase + r * STRIDE + s, base + (size_t)r * K + s);
        }
    };
    auto load_chunk = [&](int buf, int kc) {
        const uint32_t s0 = sb + buf * BUFSZ;
        const int k0 = kc * KCH;
        load_tile_a(s0, A, k0);
        load_tile_b(s0 + TILE_A, B0, k0);
        if (FUSED) load_tile_b(s0 + TILE_A + TILE_B, B1, k0);
        cp_async_commit();
    };

    // ---- per-lane ldmatrix address components (validated layout) ----
    const int lr = lid & 7;
    const int lg = lid >> 3;
    const uint32_t a_lane = (uint32_t)((warp_m + lr + (lg & 1) * 8) * STRIDE +
                                       (lg >> 1) * 16);
    const uint32_t b_lane = (uint32_t)((warp_n + lr + (lg >> 1) * 8) * STRIDE +
                                       (lg & 1) * 16);

    float accg[2][4][4];
    float accu[FUSED ? 2 : 1][4][4];
    #pragma unroll
    for (int mt = 0; mt < 2; mt++)
        #pragma unroll
        for (int nt = 0; nt < 4; nt++)
            #pragma unroll
            for (int e = 0; e < 4; e++) {
                accg[mt][nt][e] = 0.0f;
                if (FUSED) accu[mt][nt][e] = 0.0f;
            }

    const int NCH = K / KCH;
    load_chunk(0, 0);
    if (NSTAGE == 3 && NCH > 1) load_chunk(1, 1);

    for (int kc = 0; kc < NCH; ++kc) {
        const int buf = kc % NSTAGE;
        if (NSTAGE == 3) {
            if (kc + 1 < NCH) cp_async_wait<1>();
            else              cp_async_wait<0>();
            __syncthreads();
            if (kc + 2 < NCH) load_chunk((kc + 2) % NSTAGE, kc + 2);
        } else {
            if (kc + 1 < NCH) {
                load_chunk(buf ^ 1, kc + 1);
                cp_async_wait<1>();
            } else {
                cp_async_wait<0>();
            }
            __syncthreads();
        }

        const uint32_t sA  = sb + buf * BUFSZ;
        const uint32_t sBg = sA + TILE_A;
        const uint32_t sBu = sBg + TILE_B;

        #pragma unroll
        for (int ks = 0; ks < 4; ks++) {
            const uint32_t ko = ks * 32;
            // batch ALL ldsm of this step (max memory-level parallelism)
            uint32_t af[2][4], bgq[2][4], buq[2][4];
            ldsm_x4(af[0], sA + a_lane + ko);
            ldsm_x4(af[1], sA + a_lane + 16 * STRIDE + ko);
            ldsm_x4(bgq[0], sBg + b_lane + ko);
            ldsm_x4(bgq[1], sBg + b_lane + 16 * STRIDE + ko);
            if (FUSED) {
                ldsm_x4(buq[0], sBu + b_lane + ko);
                ldsm_x4(buq[1], sBu + b_lane + 16 * STRIDE + ko);
            }

            uint32_t a16[2][2][4];   // [khalf][mt][4 regs]
            #pragma unroll
            for (int mt = 0; mt < 2; mt++) {
                cvt8(af[mt][0], a16[0][mt][0], a16[0][mt][2]);
                cvt8(af[mt][1], a16[0][mt][1], a16[0][mt][3]);
                cvt8(af[mt][2], a16[1][mt][0], a16[1][mt][2]);
                cvt8(af[mt][3], a16[1][mt][1], a16[1][mt][3]);
            }

            #pragma unroll
            for (int p = 0; p < 2; p++) {
                #pragma unroll
                for (int half = 0; half < 2; half++) {
                    uint32_t B0r[2], B1r[2];
                    cvt8(bgq[p][2 * half],     B0r[0], B0r[1]);   // k 0-15
                    cvt8(bgq[p][2 * half + 1], B1r[0], B1r[1]);   // k 16-31
                    const int nt = p * 2 + half;
                    #pragma unroll
                    for (int mt = 0; mt < 2; mt++) {
                        mma_f16(accg[mt][nt], a16[0][mt], B0r);
                        mma_f16(accg[mt][nt], a16[1][mt], B1r);
                    }
                }
            }
            if (FUSED) {
                #pragma unroll
                for (int p = 0; p < 2; p++) {
                    #pragma unroll
                    for (int half = 0; half < 2; half++) {
                        uint32_t B0r[2], B1r[2];
                        cvt8(buq[p][2 * half],     B0r[0], B0r[1]);
                        cvt8(buq[p][2 * half + 1], B1r[0], B1r[1]);
                        const int nt = p * 2 + half;
                        #pragma unroll
                        for (int mt = 0; mt < 2; mt++) {
                            mma_f16(accu[mt][nt], a16[0][mt], B0r);
                            mma_f16(accu[mt][nt], a16[1][mt], B1r);
                        }
                    }
                }
            }
        }
        if (NSTAGE == 2) __syncthreads();
    }

    // ---------------- epilogue ----------------
    const int rbase = m0 + warp_m + (lid >> 2);
    const int cbase = n0 + warp_n + (lid & 3) * 2;

    if (FUSED) {
        __nv_bfloat16* out = (__nv_bfloat16*)out_v;
        const float sA = g_scale_dq[0];
        const float fG = sA * g_scale_dq[1];
        const float fU = sA * g_scale_dq[2];
        float lamax = 0.0f;
        #pragma unroll
        for (int mt = 0; mt < 2; mt++) {
            #pragma unroll
            for (int nt = 0; nt < 4; nt++) {
                #pragma unroll
                for (int half = 0; half < 2; half++) {
                    const int row = rbase + mt * 16 + half * 8;
                    const int col = cbase + nt * 8;
                    uint32_t w = 0;
                    #pragma unroll
                    for (int e = 0; e < 2; e++) {
                        // gf = bf16(acc*fG); gelu = bf16(gf * LUT[gf]) — bit-
                        // exact vs the full per-op bf16 chain.
                        __nv_bfloat16 gB = __float2bfloat16(accg[mt][nt][half * 2 + e] * fG);
                        float gf = __bfloat162float(gB);
                        float h = __bfloat162float(__ushort_as_bfloat16(
                            __ldg(&g_gelu_lut[__bfloat16_as_ushort(gB)])));
                        float gl = bf16r(gf * h);
                        float uf = bf16r(accu[mt][nt][half * 2 + e] * fU);
                        float pb = bf16r(gl * uf);
                        lamax = fmaxf(lamax, fabsf(pb));
                        w |= ((uint32_t)__bfloat16_as_ushort(__float2bfloat16(pb)))
                             << (e * 16);
                    }
                    *(uint32_t*)(out + (size_t)row * ldo + col) = w;
                }
            }
        }
        #pragma unroll
        for (int o = 16; o; o >>= 1)
            lamax = fmaxf(lamax, __shfl_xor_sync(0xffffffffu, lamax, o));
        if (lid == 0)
            atomicMax((unsigned int*)&g_amax[4], __float_as_uint(lamax));
    } else {
        // FINAL OUTPUT IS float32 (= bf16 values widened to f32)
        float* out = (float*)out_v;
        const float amax4 = fmaxf(g_amax[4], 1e-12f);
        const float s4 = bf16r(448.0f / amax4);       // bf16 scale
        const float f = bf16r(1.0f / s4) * g_scale_dq[3];
        #pragma unroll
        for (int mt = 0; mt < 2; mt++) {
            #pragma unroll
            for (int nt = 0; nt < 4; nt++) {
                #pragma unroll
                for (int half = 0; half < 2; half++) {
                    const int row = rbase + mt * 16 + half * 8;
                    const int col = cbase + nt * 8;
                    float2 w;
                    w.x = bf16r(accg[mt][nt][half * 2] * f);
                    w.y = bf16r(accg[mt][nt][half * 2 + 1] * f);
                    *(float2*)(out + (size_t)row * ldo + col) = w;
                }
            }
        }
    }
}

// ============================ launcher ======================================
extern "C" void kernel_launch(void* const* d_in, const int* in_sizes, int n_in,
                              void* d_out, int out_size) {
    const float* x  = (const float*)d_in[0];
    const float* gw = (const float*)d_in[1];
    const float* uw = (const float*)d_in[2];
    const float* dw = (const float*)d_in[3];

    void *p_xq, *p_gq, *p_uq, *p_dq, *p_inter, *p_iq;
    cudaGetSymbolAddress(&p_xq, g_xq);
    cudaGetSymbolAddress(&p_gq, g_gq);
    cudaGetSymbolAddress(&p_uq, g_uq);
    cudaGetSymbolAddress(&p_dq, g_dq);
    cudaGetSymbolAddress(&p_inter, g_inter);
    cudaGetSymbolAddress(&p_iq, g_iq);

    const int SMEM_FUSED = 2 * (TILE_A + 2 * TILE_B);  // 92160/CTA, 2-stage
    const int SMEM_PLAIN = 3 * (TILE_A + TILE_B);      // 82944/CTA, 3-stage
    cudaFuncSetAttribute((const void*)gemm_fp8_kernel<true, 2>,
                         cudaFuncAttributeMaxDynamicSharedMemorySize, SMEM_FUSED);
    cudaFuncSetAttribute((const void*)gemm_fp8_kernel<false, 3>,
                         cudaFuncAttributeMaxDynamicSharedMemorySize, SMEM_PLAIN);

    const int n4 = (T_DIM * H_DIM) / 4;  // each input tensor: 16.7M elems

    init_amax_kernel<<<1, 32>>>();
    gelu_lut_init_kernel<<<256, 256>>>();
    amax_all_kernel<<<4096, 256>>>(x, gw, uw, dw, n4);
    compute_scales_kernel<<<1, 32>>>();
    quant_all_kernel<<<2048, 256>>>(x, gw, uw, dw,
        (unsigned char*)p_xq, (unsigned char*)p_gq,
        (unsigned char*)p_uq, (unsigned char*)p_dq, n4);

    // GEMM1 fused: inter[T, I] = gelu(xq@gq^T * sxg) * (xq@uq^T * sxu) + amax
    gemm_fp8_kernel<true, 2><<<dim3(T_DIM / 64, I_DIM / 128), 256, SMEM_FUSED>>>(
        (const unsigned char*)p_xq, (const unsigned char*)p_gq,
        (const unsigned char*)p_uq, p_inter, H_DIM, I_DIM);

    quant_inter_kernel<<<4096, 256>>>((int)(((size_t)T_DIM * I_DIM) / 8));

    // GEMM2: out_f32[T, H] = widen_bf16((iq @ dq^T) * (i_s*d_s))
    gemm_fp8_kernel<false, 3><<<dim3(T_DIM / 64, H_DIM / 128), 256, SMEM_PLAIN>>>(
        (const unsigned char*)p_iq, (const unsigned char*)p_dq,
        nullptr, d_out, I_DIM, H_DIM);
}